// round 7
// baseline (speedup 1.0000x reference)
#include <cuda_runtime.h>
#include <cuda_fp16.h>
#include <math.h>
#include <stdint.h>

#define HW    16384
#define WID   128
#define CCH   192
#define C3    576
#define NB    8
#define NHEAD 4
#define CH    48
#define EPSV  1e-12f

// ---------------- scratch (device globals; allocation-free) ----------------
__device__ __align__(16) float g_cn1 [(size_t)NB*CCH*HW];
__device__ __align__(16) float g_cnf [(size_t)NB*CCH*HW];
__device__ __align__(16) float g_qkv1[(size_t)NB*C3 *HW];
__device__ __align__(16) float g_qkv [(size_t)NB*C3 *HW];
__device__ float g_alpha[NB*CCH];
__device__ float g_beta [NB*CCH];
__device__ float g_invk [NB*CCH];
__device__ float g_Gqk [(size_t)16*32*CH*CH];
__device__ float g_Gck [(size_t)16*32*CH*CH];
__device__ float g_Np  [(size_t)16*32*4*CH];
__device__ float g_attn[(size_t)NB*NHEAD*CH*CH];
__device__ float g_M   [(size_t)NB*CCH*CCH];

__device__ __forceinline__ uint32_t pack_h2(float lo, float hi) {
  __half2 h = __floats2half2_rn(lo, hi);
  return *(uint32_t*)&h;
}
__device__ __forceinline__ void mma_fp16(float* c, const uint32_t* a, const uint32_t* b) {
  asm volatile(
    "mma.sync.aligned.m16n8k16.row.col.f32.f16.f16.f32 "
    "{%0,%1,%2,%3},{%4,%5,%6,%7},{%8,%9},{%0,%1,%2,%3};"
    : "+f"(c[0]), "+f"(c[1]), "+f"(c[2]), "+f"(c[3])
    : "r"(a[0]), "r"(a[1]), "r"(a[2]), "r"(a[3]), "r"(b[0]), "r"(b[1]));
}

// ================ fp16 tensor-core GEMM (1x1 conv / batched W) ==============
// Y[b, m, n] = sum_k W_b[m,k] X_b[k,n].  CTA tile 192(M) x 128(N), BK=16.
#define AST 200
#define BST 136

__global__ __launch_bounds__(256, 1) void gemm1x1_fp16(
    const float* __restrict__ Wm, const float* __restrict__ X,
    float* __restrict__ Y, int K,
    size_t wstride, size_t xstride, size_t ystride)
{
  const int b  = blockIdx.z;
  const int m0 = blockIdx.y * 192;
  const int n0 = blockIdx.x * 128;
  const float* Wb = Wm + (size_t)b * wstride;
  const float* Xb = X + (size_t)b * xstride;
  float* Yb = Y + (size_t)b * ystride;

  __shared__ uint32_t As2[8][AST];
  __shared__ uint32_t Bs2[8][BST];

  const int t    = threadIdx.x;
  const int wid  = t >> 5, lane = t & 31;
  const int wm   = wid >> 1, wn = wid & 1;
  const int grp  = lane >> 2, t4 = lane & 3;

  float acc[3][8][4] = {};

  const int bk2 = t >> 5;
  const int bng = (t & 31) * 4;

  float4 pa[3], pb0, pb1;
  #pragma unroll
  for (int i = 0; i < 3; i++) {
    int e = t + i * 256; int row = e >> 2, kf = (e & 3) * 4;
    pa[i] = *(const float4*)&Wb[(size_t)(m0 + row) * K + kf];
  }
  pb0 = *(const float4*)&Xb[(size_t)(2 * bk2    ) * HW + n0 + bng];
  pb1 = *(const float4*)&Xb[(size_t)(2 * bk2 + 1) * HW + n0 + bng];
  #pragma unroll
  for (int i = 0; i < 3; i++) {
    int e = t + i * 256; int row = e >> 2, k2 = (e & 3) * 2;
    As2[k2  ][row] = pack_h2(pa[i].x, pa[i].y);
    As2[k2+1][row] = pack_h2(pa[i].z, pa[i].w);
  }
  {
    uint4 u = make_uint4(pack_h2(pb0.x, pb1.x), pack_h2(pb0.y, pb1.y),
                         pack_h2(pb0.z, pb1.z), pack_h2(pb0.w, pb1.w));
    *(uint4*)&Bs2[bk2][bng] = u;
  }
  __syncthreads();

  for (int k0 = 0; k0 < K; k0 += 16) {
    bool more = (k0 + 16) < K;
    if (more) {
      #pragma unroll
      for (int i = 0; i < 3; i++) {
        int e = t + i * 256; int row = e >> 2, kf = (e & 3) * 4;
        pa[i] = *(const float4*)&Wb[(size_t)(m0 + row) * K + k0 + 16 + kf];
      }
      pb0 = *(const float4*)&Xb[(size_t)(k0 + 16 + 2 * bk2    ) * HW + n0 + bng];
      pb1 = *(const float4*)&Xb[(size_t)(k0 + 16 + 2 * bk2 + 1) * HW + n0 + bng];
    }
    {
      uint32_t af[3][4], bf[8][2];
      #pragma unroll
      for (int mt = 0; mt < 3; mt++) {
        int mb = wm * 48 + mt * 16 + grp;
        af[mt][0] = As2[t4    ][mb];     af[mt][1] = As2[t4    ][mb + 8];
        af[mt][2] = As2[t4 + 4][mb];     af[mt][3] = As2[t4 + 4][mb + 8];
      }
      #pragma unroll
      for (int nt = 0; nt < 8; nt++) {
        int nb = wn * 64 + nt * 8 + grp;
        bf[nt][0] = Bs2[t4][nb]; bf[nt][1] = Bs2[t4 + 4][nb];
      }
      #pragma unroll
      for (int mt = 0; mt < 3; mt++)
        #pragma unroll
        for (int nt = 0; nt < 8; nt++)
          mma_fp16(acc[mt][nt], af[mt], bf[nt]);
    }
    __syncthreads();
    if (more) {
      #pragma unroll
      for (int i = 0; i < 3; i++) {
        int e = t + i * 256; int row = e >> 2, k2 = (e & 3) * 2;
        As2[k2  ][row] = pack_h2(pa[i].x, pa[i].y);
        As2[k2+1][row] = pack_h2(pa[i].z, pa[i].w);
      }
      uint4 u = make_uint4(pack_h2(pb0.x, pb1.x), pack_h2(pb0.y, pb1.y),
                           pack_h2(pb0.z, pb1.z), pack_h2(pb0.w, pb1.w));
      *(uint4*)&Bs2[bk2][bng] = u;
      __syncthreads();
    }
  }

  #pragma unroll
  for (int mt = 0; mt < 3; mt++) {
    #pragma unroll
    for (int nt = 0; nt < 8; nt++) {
      int mr = m0 + wm * 48 + mt * 16 + grp;
      int nc = n0 + wn * 64 + nt * 8 + t4 * 2;
      *(float2*)&Yb[(size_t)mr * HW + nc] = make_float2(acc[mt][nt][0], acc[mt][nt][1]);
      *(float2*)&Yb[(size_t)(mr + 8) * HW + nc] = make_float2(acc[mt][nt][2], acc[mt][nt][3]);
    }
  }
}

// ========== fp16 conv3x3 via tap decomposition (shared halo tile) ===========
// Y[m, y, :] = sum_{tap, c} W[m][c*9+tap] * X[c][y+dy][x+dx].
// Per 16-channel chunk: load Xh[8 k-pairs][3 rows][136] (half2) once; run 9
// taps as shifted-fragment MMAs. A double-buffered in smem; 1 sync per tap.
#define XST 136

__global__ __launch_bounds__(256, 1) void conv3x3_tap(
    const float* __restrict__ Wm, const float* __restrict__ X,
    float* __restrict__ Y)
{
  const int Ktot = CCH * 9;
  const int b = blockIdx.z;
  const int y = blockIdx.x;
  const float* Xb = X + (size_t)b * CCH * HW;
  float* Yb = Y + (size_t)b * CCH * HW;

  __shared__ uint32_t Xh[8][3][XST];      // 13056 B
  __shared__ uint32_t As2[2][8][AST];     // 12800 B

  const int t   = threadIdx.x;
  const int wid = t >> 5, lane = t & 31;
  const int wm  = wid >> 1, wn = wid & 1;
  const int grp = lane >> 2, t4 = lane & 3;

  float acc[3][8][4] = {};

  auto fillX = [&](int cc) {
    const int c0 = cc * 16;
    for (int w = t; w < 8 * 3 * XST; w += 256) {
      int j = w / (3 * XST);
      int rem = w - j * (3 * XST);
      int yr = rem / XST;
      int xx = rem - yr * XST;
      int yy = y + yr - 1;
      int xc = xx - 1;
      float v0 = 0.f, v1 = 0.f;
      if (yy >= 0 && yy < WID && xc >= 0 && xc < WID) {
        const float* pp = Xb + (size_t)(c0 + 2 * j) * HW + yy * WID + xc;
        v0 = pp[0]; v1 = pp[HW];
      }
      Xh[j][yr][xx] = pack_h2(v0, v1);
    }
  };

  // prologue: A for tt=0 into buf 0, Xh for chunk 0
  #pragma unroll
  for (int i = 0; i < 6; i++) {
    int w = t + i * 256; int kc2 = w / 192, m = w - kc2 * 192;
    int kk = (2 * kc2) * 9;               // chunk 0, tap 0
    As2[0][kc2][m] = pack_h2(Wm[(size_t)m * Ktot + kk],
                             Wm[(size_t)m * Ktot + kk + 9]);
  }
  fillX(0);
  __syncthreads();

  for (int tt = 0; tt < 108; tt++) {
    const int p = tt & 1;
    const int cc = tt / 9;
    const int tap = tt - cc * 9;
    const int yr = tap / 3, dx = tap - yr * 3;

    // prefetch A for tt+1 into regs
    uint32_t paw[6];
    if (tt < 107) {
      int t2 = tt + 1;
      int c2 = t2 / 9, tp2 = t2 - c2 * 9;
      #pragma unroll
      for (int i = 0; i < 6; i++) {
        int w = t + i * 256; int kc2 = w / 192, m = w - kc2 * 192;
        int kk = (c2 * 16 + 2 * kc2) * 9 + tp2;
        paw[i] = pack_h2(Wm[(size_t)m * Ktot + kk],
                         Wm[(size_t)m * Ktot + kk + 9]);
      }
    }

    // compute
    {
      uint32_t af[3][4], bf[8][2];
      #pragma unroll
      for (int mt = 0; mt < 3; mt++) {
        int mb = wm * 48 + mt * 16 + grp;
        af[mt][0] = As2[p][t4    ][mb]; af[mt][1] = As2[p][t4    ][mb + 8];
        af[mt][2] = As2[p][t4 + 4][mb]; af[mt][3] = As2[p][t4 + 4][mb + 8];
      }
      #pragma unroll
      for (int nt = 0; nt < 8; nt++) {
        int nx = wn * 64 + nt * 8 + grp + dx;
        bf[nt][0] = Xh[t4][yr][nx]; bf[nt][1] = Xh[t4 + 4][yr][nx];
      }
      #pragma unroll
      for (int mt = 0; mt < 3; mt++)
        #pragma unroll
        for (int nt = 0; nt < 8; nt++)
          mma_fp16(acc[mt][nt], af[mt], bf[nt]);
    }

    // store prefetched A into the other buffer
    if (tt < 107) {
      #pragma unroll
      for (int i = 0; i < 6; i++) {
        int w = t + i * 256; int kc2 = w / 192, m = w - kc2 * 192;
        As2[1 - p][kc2][m] = paw[i];
      }
    }
    __syncthreads();
    if (tap == 8 && tt < 107) {
      fillX(cc + 1);
      __syncthreads();
    }
  }

  const int n0 = y * 128;
  #pragma unroll
  for (int mt = 0; mt < 3; mt++) {
    #pragma unroll
    for (int nt = 0; nt < 8; nt++) {
      int mr = wm * 48 + mt * 16 + grp;
      int nc = n0 + wn * 64 + nt * 8 + t4 * 2;
      *(float2*)&Yb[(size_t)mr * HW + nc] = make_float2(acc[mt][nt][0], acc[mt][nt][1]);
      *(float2*)&Yb[(size_t)(mr + 8) * HW + nc] = make_float2(acc[mt][nt][2], acc[mt][nt][3]);
    }
  }
}

// ---------------- depthwise 3x3 (groups = 3C), 4 outputs/thread -------------
__global__ __launch_bounds__(256) void dwconv4_k(
    const float* __restrict__ in, const float* __restrict__ w,
    float* __restrict__ out)
{
  size_t i4 = (size_t)blockIdx.x * 256 + threadIdx.x;
  size_t base = i4 * 4;
  int s  = (int)(base & (HW - 1));
  size_t bc = base >> 14;
  int c = (int)(bc % C3);
  int y = s >> 7, x0 = s & 127;
  const float* wp = w + (size_t)c * 9;
  const float* ip = in + (base - s);
  float w0=wp[0],w1=wp[1],w2=wp[2],w3=wp[3],w4=wp[4],w5=wp[5],w6=wp[6],w7=wp[7],w8=wp[8];
  float a0=0,a1=0,a2=0,a3=0;
  #pragma unroll
  for (int dy = -1; dy <= 1; dy++) {
    int yy = y + dy;
    if (yy < 0 || yy >= WID) continue;
    const float* row = ip + yy * WID;
    float4 cv = *(const float4*)&row[x0];
    float lf = (x0 > 0)   ? row[x0 - 1] : 0.f;
    float rt = (x0 < 124) ? row[x0 + 4] : 0.f;
    float r0, r1, r2;
    if (dy < 0)      { r0 = w0; r1 = w1; r2 = w2; }
    else if (dy==0)  { r0 = w3; r1 = w4; r2 = w5; }
    else             { r0 = w6; r1 = w7; r2 = w8; }
    a0 += r0*lf   + r1*cv.x + r2*cv.y;
    a1 += r0*cv.x + r1*cv.y + r2*cv.z;
    a2 += r0*cv.y + r1*cv.z + r2*cv.w;
    a3 += r0*cv.z + r1*cv.w + r2*rt;
  }
  *(float4*)&out[base] = make_float4(a0, a1, a2, a3);
}

// ---- logits: raw Grams Gqk = q k^T, Gck = cn k^T + per-channel norm partials
__global__ __launch_bounds__(256) void logits2_k(
    const float* __restrict__ qkv, const float* __restrict__ cnf,
    float* __restrict__ Gqk, float* __restrict__ Gck, float* __restrict__ Np)
{
  int bh = blockIdx.y; int b = bh >> 2, h = bh & 3;
  int chunk = blockIdx.x;
  int s0 = chunk * 1024;
  const float* Q  = qkv + ((size_t)b*C3 + h*CH) * HW;
  const float* Kp = qkv + ((size_t)b*C3 + CCH + h*CH) * HW;
  const float* Cn = cnf + ((size_t)b*CCH + h*CH) * HW;
  __shared__ float Qs[48][68];
  __shared__ float Ks[48][68];
  __shared__ float Cs[48][68];
  const int t = threadIdx.x;
  const int tx = t & 15, ty = t >> 4;
  float aqk[3][3] = {}, ack[3][3] = {};
  float psq[3] = {}, psk[3] = {}, psc[3] = {}, psd[3] = {};
  for (int sc = 0; sc < 1024; sc += 64) {
    #pragma unroll
    for (int i = 0; i < 3; i++) {
      int e = t + i * 256;
      int row = e >> 4;
      int col = (e & 15) * 4;
      float4 q4 = *(const float4*)&Q [(size_t)row*HW + s0 + sc + col];
      float4 c4 = *(const float4*)&Cn[(size_t)row*HW + s0 + sc + col];
      float4 k4 = *(const float4*)&Kp[(size_t)row*HW + s0 + sc + col];
      *(float4*)&Qs[row][col] = q4;
      *(float4*)&Cs[row][col] = c4;
      *(float4*)&Ks[row][col] = k4;
      psq[i] += q4.x*q4.x + q4.y*q4.y + q4.z*q4.z + q4.w*q4.w;
      psk[i] += k4.x*k4.x + k4.y*k4.y + k4.z*k4.z + k4.w*k4.w;
      psc[i] += c4.x*c4.x + c4.y*c4.y + c4.z*c4.z + c4.w*c4.w;
      psd[i] += q4.x*c4.x + q4.y*c4.y + q4.z*c4.z + q4.w*c4.w;
    }
    __syncthreads();
    #pragma unroll 4
    for (int s = 0; s < 64; s++) {
      float qv0 = Qs[ty*3+0][s], qv1 = Qs[ty*3+1][s], qv2 = Qs[ty*3+2][s];
      float cv0 = Cs[ty*3+0][s], cv1 = Cs[ty*3+1][s], cv2 = Cs[ty*3+2][s];
      float kv0 = Ks[tx*3+0][s], kv1 = Ks[tx*3+1][s], kv2 = Ks[tx*3+2][s];
      aqk[0][0]+=qv0*kv0; aqk[0][1]+=qv0*kv1; aqk[0][2]+=qv0*kv2;
      aqk[1][0]+=qv1*kv0; aqk[1][1]+=qv1*kv1; aqk[1][2]+=qv1*kv2;
      aqk[2][0]+=qv2*kv0; aqk[2][1]+=qv2*kv1; aqk[2][2]+=qv2*kv2;
      ack[0][0]+=cv0*kv0; ack[0][1]+=cv0*kv1; ack[0][2]+=cv0*kv2;
      ack[1][0]+=cv1*kv0; ack[1][1]+=cv1*kv1; ack[1][2]+=cv1*kv2;
      ack[2][0]+=cv2*kv0; ack[2][1]+=cv2*kv1; ack[2][2]+=cv2*kv2;
    }
    __syncthreads();
  }
  size_t gbase = ((size_t)chunk * 32 + bh) * CH * CH;
  #pragma unroll
  for (int i = 0; i < 3; i++)
    #pragma unroll
    for (int j = 0; j < 3; j++) {
      Gqk[gbase + (size_t)(ty*3+i)*CH + tx*3+j] = aqk[i][j];
      Gck[gbase + (size_t)(ty*3+i)*CH + tx*3+j] = ack[i][j];
    }
  // reduce norm partials across the 16 threads sharing each row
  #pragma unroll
  for (int i = 0; i < 3; i++) {
    int row = (t + i * 256) >> 4;
    float vq = psq[i], vk = psk[i], vc = psc[i], vd = psd[i];
    #pragma unroll
    for (int o = 8; o > 0; o >>= 1) {
      vq += __shfl_down_sync(0xffffffffu, vq, o, 16);
      vk += __shfl_down_sync(0xffffffffu, vk, o, 16);
      vc += __shfl_down_sync(0xffffffffu, vc, o, 16);
      vd += __shfl_down_sync(0xffffffffu, vd, o, 16);
    }
    if ((t & 15) == 0) {
      size_t nb = (((size_t)chunk * 32 + bh) * 4) * CH;
      Np[nb + 0*CH + row] = vq;
      Np[nb + 1*CH + row] = vk;
      Np[nb + 2*CH + row] = vc;
      Np[nb + 3*CH + row] = vd;
    }
  }
}

// ---------------- scalars: reduce norm partials -> alpha, beta, invk --------
__global__ __launch_bounds__(48) void scalars_k(
    const float* __restrict__ Np, float* __restrict__ alpha,
    float* __restrict__ beta, float* __restrict__ invk)
{
  int bh = blockIdx.x; int b = bh >> 2, h = bh & 3;
  int c = threadIdx.x;
  float Sq = 0, Sk = 0, Sc = 0, Sd = 0;
  for (int ch = 0; ch < 16; ch++) {
    size_t nb = (((size_t)ch * 32 + bh) * 4) * CH;
    Sq += Np[nb + 0*CH + c];
    Sk += Np[nb + 1*CH + c];
    Sc += Np[nb + 2*CH + c];
    Sd += Np[nb + 3*CH + c];
  }
  float a  = fmaxf(sqrtf(Sq), EPSV);
  float bb = fmaxf(sqrtf(Sc), EPSV);
  float n2 = Sq/(a*a) + 2.f*Sd/(a*bb) + Sc/(bb*bb);
  float dn = fmaxf(sqrtf(fmaxf(n2, 0.f)), EPSV);
  int bc = b*CCH + h*CH + c;
  alpha[bc] = 1.f / (a * dn);
  beta [bc] = 1.f / (bb * dn);
  invk [bc] = 1.f / fmaxf(sqrtf(Sk), EPSV);
}

// ---------------- softmax over d of t*ik_d*(al_c Gqk + be_c Gck) ------------
__global__ __launch_bounds__(32) void softmax2_k(
    const float* __restrict__ Gqk, const float* __restrict__ Gck,
    const float* __restrict__ alpha, const float* __restrict__ beta,
    const float* __restrict__ invk, const float* __restrict__ temp,
    float* __restrict__ attn)
{
  int row = blockIdx.x;            // bh*48 + c
  int bh = row / CH;
  int c  = row - bh * CH;
  int b  = bh >> 2, h = bh & 3;
  int lane = threadIdx.x;
  float tv = temp[h];
  float al = alpha[b*CCH + h*CH + c];
  float be = beta [b*CCH + h*CH + c];
  bool has1 = (lane + 32) < CH;
  float ik0 = invk[b*CCH + h*CH + lane];
  float ik1 = has1 ? invk[b*CCH + h*CH + lane + 32] : 0.f;
  float gq0 = 0, gc0 = 0, gq1 = 0, gc1 = 0;
  for (int ch = 0; ch < 16; ch++) {
    size_t base = (((size_t)ch*32 + bh)*CH + c)*CH;
    gq0 += Gqk[base + lane]; gc0 += Gck[base + lane];
    if (has1) { gq1 += Gqk[base + lane + 32]; gc1 += Gck[base + lane + 32]; }
  }
  float v0 = (al * gq0 + be * gc0) * ik0 * tv;
  float v1 = (al * gq1 + be * gc1) * ik1 * tv;
  float m = has1 ? fmaxf(v0, v1) : v0;
  #pragma unroll
  for (int o = 16; o > 0; o >>= 1) m = fmaxf(m, __shfl_xor_sync(0xffffffffu, m, o));
  float e0 = __expf(v0 - m);
  float e1 = has1 ? __expf(v1 - m) : 0.f;
  float s = e0 + e1;
  #pragma unroll
  for (int o = 16; o > 0; o >>= 1) s += __shfl_xor_sync(0xffffffffu, s, o);
  float inv = 1.f / s;
  attn[(size_t)row*CH + lane] = e0 * inv;
  if (has1) attn[(size_t)row*CH + lane + 32] = e1 * inv;
}

// ---------------- M = P @ blockdiag(attn): per-batch fused proj weights ----
__global__ __launch_bounds__(192) void pa_k(
    const float* __restrict__ P, const float* __restrict__ attn,
    float* __restrict__ M)
{
  int bh = blockIdx.x; int b = bh >> 2, h = bh & 3;
  __shared__ float As[48][49];
  const int t = threadIdx.x;
  for (int e = t; e < 48*48; e += 192)
    As[e / 48][e % 48] = attn[(size_t)bh * CH * CH + e];
  __syncthreads();
  float pr[48];
  #pragma unroll
  for (int c = 0; c < 48; c++)
    pr[c] = P[(size_t)t * CCH + h * CH + c];
  #pragma unroll 4
  for (int d = 0; d < 48; d++) {
    float s = 0.f;
    #pragma unroll
    for (int c = 0; c < 48; c++) s += pr[c] * As[c][d];
    M[((size_t)b * CCH + t) * CCH + h * CH + d] = s;
  }
}

// ---------------- launch -----------------------------------------------------
extern "C" void kernel_launch(void* const* d_in, const int* in_sizes, int n_in,
                              void* d_out, int out_size)
{
  const float* x        = (const float*)d_in[0];
  const float* cn       = (const float*)d_in[1];
  const float* cn_w1    = (const float*)d_in[2];
  const float* cn_w3    = (const float*)d_in[3];
  const float* qkv_w    = (const float*)d_in[4];
  const float* qkv_dw_w = (const float*)d_in[5];
  const float* proj_w   = (const float*)d_in[6];
  const float* temp     = (const float*)d_in[7];
  float* out = (float*)d_out;

  float *cn1, *cnf, *qkv1, *qkv, *al, *be, *ik, *Gqk, *Gck, *Np, *at, *Mw;
  cudaGetSymbolAddress((void**)&cn1,  g_cn1);
  cudaGetSymbolAddress((void**)&cnf,  g_cnf);
  cudaGetSymbolAddress((void**)&qkv1, g_qkv1);
  cudaGetSymbolAddress((void**)&qkv,  g_qkv);
  cudaGetSymbolAddress((void**)&al,   g_alpha);
  cudaGetSymbolAddress((void**)&be,   g_beta);
  cudaGetSymbolAddress((void**)&ik,   g_invk);
  cudaGetSymbolAddress((void**)&Gqk,  g_Gqk);
  cudaGetSymbolAddress((void**)&Gck,  g_Gck);
  cudaGetSymbolAddress((void**)&Np,   g_Np);
  cudaGetSymbolAddress((void**)&at,   g_attn);
  cudaGetSymbolAddress((void**)&Mw,   g_M);

  dim3 g1(HW/128, 1, NB);
  gemm1x1_fp16<<<g1, 256>>>(cn_w1, cn, cn1, CCH,
                            0, (size_t)CCH*HW, (size_t)CCH*HW);
  conv3x3_tap<<<g1, 256>>>(cn_w3, cn1, cnf);

  dim3 g2(HW/128, 3, NB);
  gemm1x1_fp16<<<g2, 256>>>(qkv_w, x, qkv1, CCH,
                            0, (size_t)CCH*HW, (size_t)C3*HW);

  size_t ndw4 = (size_t)NB * C3 * HW / 4;
  dwconv4_k<<<(unsigned)(ndw4 / 256), 256>>>(qkv1, qkv_dw_w, qkv);

  logits2_k<<<dim3(16, NB*NHEAD), 256>>>(qkv, cnf, Gqk, Gck, Np);
  scalars_k<<<NB*NHEAD, 48>>>(Np, al, be, ik);
  softmax2_k<<<NB*NHEAD*CH, 32>>>(Gqk, Gck, al, be, ik, temp, at);
  pa_k<<<NB*NHEAD, 192>>>(proj_w, at, Mw);

  // fused (attn@v + proj): out_b = M_b @ v_b
  gemm1x1_fp16<<<g1, 256>>>(Mw, qkv + (size_t)2*CCH*HW, out, CCH,
                            (size_t)CCH*CCH, (size_t)C3*HW, (size_t)CCH*HW);
}

// round 8
// speedup vs baseline: 2.7153x; 2.7153x over previous
#include <cuda_runtime.h>
#include <cuda_fp16.h>
#include <math.h>
#include <stdint.h>

#define HW    16384
#define WID   128
#define CCH   192
#define C3    576
#define NB    8
#define NHEAD 4
#define CH    48
#define EPSV  1e-12f

// ---------------- scratch (device globals; allocation-free) ----------------
__device__ __align__(16) float g_cn1 [(size_t)NB*CCH*HW];
__device__ __align__(16) float g_cnf [(size_t)NB*CCH*HW];
__device__ __align__(16) float g_qkv1[(size_t)NB*C3 *HW];
__device__ __align__(16) float g_qkv [(size_t)NB*C3 *HW];
__device__ float g_alpha[NB*CCH];
__device__ float g_beta [NB*CCH];
__device__ float g_invk [NB*CCH];
__device__ float g_Gqk [(size_t)16*32*CH*CH];
__device__ float g_Gck [(size_t)16*32*CH*CH];
__device__ float g_Np  [(size_t)16*32*4*CH];
__device__ float g_attn[(size_t)NB*NHEAD*CH*CH];
__device__ float g_M   [(size_t)NB*CCH*CCH];

__device__ __forceinline__ uint32_t pack_h2(float lo, float hi) {
  __half2 h = __floats2half2_rn(lo, hi);
  return *(uint32_t*)&h;
}
__device__ __forceinline__ void mma_fp16(float* c, const uint32_t* a, const uint32_t* b) {
  asm volatile(
    "mma.sync.aligned.m16n8k16.row.col.f32.f16.f16.f32 "
    "{%0,%1,%2,%3},{%4,%5,%6,%7},{%8,%9},{%0,%1,%2,%3};"
    : "+f"(c[0]), "+f"(c[1]), "+f"(c[2]), "+f"(c[3])
    : "r"(a[0]), "r"(a[1]), "r"(a[2]), "r"(a[3]), "r"(b[0]), "r"(b[1]));
}

// ================ fp16 tensor-core GEMM (1x1 conv / batched W) ==============
// Y[b, m, n] = sum_k W_b[m,k] X_b[k,n].  CTA tile 192(M) x 128(N), BK=16.
#define AST 200
#define BST 136

__global__ __launch_bounds__(256, 1) void gemm1x1_fp16(
    const float* __restrict__ Wm, const float* __restrict__ X,
    float* __restrict__ Y, int K,
    size_t wstride, size_t xstride, size_t ystride)
{
  const int b  = blockIdx.z;
  const int m0 = blockIdx.y * 192;
  const int n0 = blockIdx.x * 128;
  const float* Wb = Wm + (size_t)b * wstride;
  const float* Xb = X + (size_t)b * xstride;
  float* Yb = Y + (size_t)b * ystride;

  __shared__ uint32_t As2[8][AST];
  __shared__ uint32_t Bs2[8][BST];

  const int t    = threadIdx.x;
  const int wid  = t >> 5, lane = t & 31;
  const int wm   = wid >> 1, wn = wid & 1;
  const int grp  = lane >> 2, t4 = lane & 3;

  float acc[3][8][4] = {};

  const int bk2 = t >> 5;
  const int bng = (t & 31) * 4;

  float4 pa[3], pb0, pb1;
  #pragma unroll
  for (int i = 0; i < 3; i++) {
    int e = t + i * 256; int row = e >> 2, kf = (e & 3) * 4;
    pa[i] = *(const float4*)&Wb[(size_t)(m0 + row) * K + kf];
  }
  pb0 = *(const float4*)&Xb[(size_t)(2 * bk2    ) * HW + n0 + bng];
  pb1 = *(const float4*)&Xb[(size_t)(2 * bk2 + 1) * HW + n0 + bng];
  #pragma unroll
  for (int i = 0; i < 3; i++) {
    int e = t + i * 256; int row = e >> 2, k2 = (e & 3) * 2;
    As2[k2  ][row] = pack_h2(pa[i].x, pa[i].y);
    As2[k2+1][row] = pack_h2(pa[i].z, pa[i].w);
  }
  {
    uint4 u = make_uint4(pack_h2(pb0.x, pb1.x), pack_h2(pb0.y, pb1.y),
                         pack_h2(pb0.z, pb1.z), pack_h2(pb0.w, pb1.w));
    *(uint4*)&Bs2[bk2][bng] = u;
  }
  __syncthreads();

  for (int k0 = 0; k0 < K; k0 += 16) {
    bool more = (k0 + 16) < K;
    if (more) {
      #pragma unroll
      for (int i = 0; i < 3; i++) {
        int e = t + i * 256; int row = e >> 2, kf = (e & 3) * 4;
        pa[i] = *(const float4*)&Wb[(size_t)(m0 + row) * K + k0 + 16 + kf];
      }
      pb0 = *(const float4*)&Xb[(size_t)(k0 + 16 + 2 * bk2    ) * HW + n0 + bng];
      pb1 = *(const float4*)&Xb[(size_t)(k0 + 16 + 2 * bk2 + 1) * HW + n0 + bng];
    }
    {
      uint32_t af[3][4], bf[8][2];
      #pragma unroll
      for (int mt = 0; mt < 3; mt++) {
        int mb = wm * 48 + mt * 16 + grp;
        af[mt][0] = As2[t4    ][mb];     af[mt][1] = As2[t4    ][mb + 8];
        af[mt][2] = As2[t4 + 4][mb];     af[mt][3] = As2[t4 + 4][mb + 8];
      }
      #pragma unroll
      for (int nt = 0; nt < 8; nt++) {
        int nb = wn * 64 + nt * 8 + grp;
        bf[nt][0] = Bs2[t4][nb]; bf[nt][1] = Bs2[t4 + 4][nb];
      }
      #pragma unroll
      for (int mt = 0; mt < 3; mt++)
        #pragma unroll
        for (int nt = 0; nt < 8; nt++)
          mma_fp16(acc[mt][nt], af[mt], bf[nt]);
    }
    __syncthreads();
    if (more) {
      #pragma unroll
      for (int i = 0; i < 3; i++) {
        int e = t + i * 256; int row = e >> 2, k2 = (e & 3) * 2;
        As2[k2  ][row] = pack_h2(pa[i].x, pa[i].y);
        As2[k2+1][row] = pack_h2(pa[i].z, pa[i].w);
      }
      uint4 u = make_uint4(pack_h2(pb0.x, pb1.x), pack_h2(pb0.y, pb1.y),
                           pack_h2(pb0.z, pb1.z), pack_h2(pb0.w, pb1.w));
      *(uint4*)&Bs2[bk2][bng] = u;
      __syncthreads();
    }
  }

  #pragma unroll
  for (int mt = 0; mt < 3; mt++) {
    #pragma unroll
    for (int nt = 0; nt < 8; nt++) {
      int mr = m0 + wm * 48 + mt * 16 + grp;
      int nc = n0 + wn * 64 + nt * 8 + t4 * 2;
      *(float2*)&Yb[(size_t)mr * HW + nc] = make_float2(acc[mt][nt][0], acc[mt][nt][1]);
      *(float2*)&Yb[(size_t)(mr + 8) * HW + nc] = make_float2(acc[mt][nt][2], acc[mt][nt][3]);
    }
  }
}

// ============= fp16 tensor-core implicit-GEMM 3x3 conv (R5 proven) ==========
// K = 192*9 = 1728. N tile = 128 = one full image row (y = blockIdx.x).
__global__ __launch_bounds__(256, 1) void conv3x3_fp16(
    const float* __restrict__ Wm, const float* __restrict__ X,
    float* __restrict__ Y)
{
  const int Ktot = CCH * 9;
  const int b = blockIdx.z;
  const int y = blockIdx.x;
  const float* Xb = X + (size_t)b * CCH * HW;
  float* Yb = Y + (size_t)b * CCH * HW;

  __shared__ uint32_t As2[8][AST];
  __shared__ uint32_t Bs2[8][BST];

  const int t   = threadIdx.x;
  const int wid = t >> 5, lane = t & 31;
  const int wm  = wid >> 1, wn = wid & 1;
  const int grp = lane >> 2, t4 = lane & 3;

  float acc[3][8][4] = {};

  const int bk2 = t >> 5;
  const int bng = (t & 31) * 4;

  auto gatherB = [&](int kglob, float* o) {
    int ci = kglob / 9;
    int r  = kglob - ci * 9;
    int ky = r / 3;
    int kx = r - ky * 3;
    int yy = y + ky - 1;
    bool rowok = (yy >= 0) & (yy < WID);
    const float* src = Xb + (size_t)ci * HW + yy * WID;
    #pragma unroll
    for (int j = 0; j < 4; j++) {
      int xx = bng + j + kx - 1;
      o[j] = (rowok && xx >= 0 && xx < WID) ? src[xx] : 0.f;
    }
  };

  float4 pa[3];
  float pb0[4], pb1[4];
  #pragma unroll
  for (int i = 0; i < 3; i++) {
    int e = t + i * 256; int row = e >> 2, kf = (e & 3) * 4;
    pa[i] = *(const float4*)&Wm[(size_t)row * Ktot + kf];
  }
  gatherB(2 * bk2, pb0);
  gatherB(2 * bk2 + 1, pb1);
  #pragma unroll
  for (int i = 0; i < 3; i++) {
    int e = t + i * 256; int row = e >> 2, k2 = (e & 3) * 2;
    As2[k2  ][row] = pack_h2(pa[i].x, pa[i].y);
    As2[k2+1][row] = pack_h2(pa[i].z, pa[i].w);
  }
  {
    uint4 u = make_uint4(pack_h2(pb0[0], pb1[0]), pack_h2(pb0[1], pb1[1]),
                         pack_h2(pb0[2], pb1[2]), pack_h2(pb0[3], pb1[3]));
    *(uint4*)&Bs2[bk2][bng] = u;
  }
  __syncthreads();

  for (int k0 = 0; k0 < Ktot; k0 += 16) {
    bool more = (k0 + 16) < Ktot;
    if (more) {
      #pragma unroll
      for (int i = 0; i < 3; i++) {
        int e = t + i * 256; int row = e >> 2, kf = (e & 3) * 4;
        pa[i] = *(const float4*)&Wm[(size_t)row * Ktot + k0 + 16 + kf];
      }
      gatherB(k0 + 16 + 2 * bk2, pb0);
      gatherB(k0 + 16 + 2 * bk2 + 1, pb1);
    }
    {
      uint32_t af[3][4], bf[8][2];
      #pragma unroll
      for (int mt = 0; mt < 3; mt++) {
        int mb = wm * 48 + mt * 16 + grp;
        af[mt][0] = As2[t4    ][mb];     af[mt][1] = As2[t4    ][mb + 8];
        af[mt][2] = As2[t4 + 4][mb];     af[mt][3] = As2[t4 + 4][mb + 8];
      }
      #pragma unroll
      for (int nt = 0; nt < 8; nt++) {
        int nb = wn * 64 + nt * 8 + grp;
        bf[nt][0] = Bs2[t4][nb]; bf[nt][1] = Bs2[t4 + 4][nb];
      }
      #pragma unroll
      for (int mt = 0; mt < 3; mt++)
        #pragma unroll
        for (int nt = 0; nt < 8; nt++)
          mma_fp16(acc[mt][nt], af[mt], bf[nt]);
    }
    __syncthreads();
    if (more) {
      #pragma unroll
      for (int i = 0; i < 3; i++) {
        int e = t + i * 256; int row = e >> 2, k2 = (e & 3) * 2;
        As2[k2  ][row] = pack_h2(pa[i].x, pa[i].y);
        As2[k2+1][row] = pack_h2(pa[i].z, pa[i].w);
      }
      uint4 u = make_uint4(pack_h2(pb0[0], pb1[0]), pack_h2(pb0[1], pb1[1]),
                           pack_h2(pb0[2], pb1[2]), pack_h2(pb0[3], pb1[3]));
      *(uint4*)&Bs2[bk2][bng] = u;
      __syncthreads();
    }
  }

  const int n0 = y * 128;
  #pragma unroll
  for (int mt = 0; mt < 3; mt++) {
    #pragma unroll
    for (int nt = 0; nt < 8; nt++) {
      int mr = wm * 48 + mt * 16 + grp;
      int nc = n0 + wn * 64 + nt * 8 + t4 * 2;
      *(float2*)&Yb[(size_t)mr * HW + nc] = make_float2(acc[mt][nt][0], acc[mt][nt][1]);
      *(float2*)&Yb[(size_t)(mr + 8) * HW + nc] = make_float2(acc[mt][nt][2], acc[mt][nt][3]);
    }
  }
}

// ---------------- depthwise 3x3 (groups = 3C), 4 outputs/thread -------------
__global__ __launch_bounds__(256) void dwconv4_k(
    const float* __restrict__ in, const float* __restrict__ w,
    float* __restrict__ out)
{
  size_t i4 = (size_t)blockIdx.x * 256 + threadIdx.x;
  size_t base = i4 * 4;
  int s  = (int)(base & (HW - 1));
  size_t bc = base >> 14;
  int c = (int)(bc % C3);
  int y = s >> 7, x0 = s & 127;
  const float* wp = w + (size_t)c * 9;
  const float* ip = in + (base - s);
  float w0=wp[0],w1=wp[1],w2=wp[2],w3=wp[3],w4=wp[4],w5=wp[5],w6=wp[6],w7=wp[7],w8=wp[8];
  float a0=0,a1=0,a2=0,a3=0;
  #pragma unroll
  for (int dy = -1; dy <= 1; dy++) {
    int yy = y + dy;
    if (yy < 0 || yy >= WID) continue;
    const float* row = ip + yy * WID;
    float4 cv = *(const float4*)&row[x0];
    float lf = (x0 > 0)   ? row[x0 - 1] : 0.f;
    float rt = (x0 < 124) ? row[x0 + 4] : 0.f;
    float r0, r1, r2;
    if (dy < 0)      { r0 = w0; r1 = w1; r2 = w2; }
    else if (dy==0)  { r0 = w3; r1 = w4; r2 = w5; }
    else             { r0 = w6; r1 = w7; r2 = w8; }
    a0 += r0*lf   + r1*cv.x + r2*cv.y;
    a1 += r0*cv.x + r1*cv.y + r2*cv.z;
    a2 += r0*cv.y + r1*cv.z + r2*cv.w;
    a3 += r0*cv.z + r1*cv.w + r2*rt;
  }
  *(float4*)&out[base] = make_float4(a0, a1, a2, a3);
}

// ---- logits: raw Grams Gqk = q k^T, Gck = cn k^T + per-channel norm partials
__global__ __launch_bounds__(256) void logits2_k(
    const float* __restrict__ qkv, const float* __restrict__ cnf,
    float* __restrict__ Gqk, float* __restrict__ Gck, float* __restrict__ Np)
{
  int bh = blockIdx.y; int b = bh >> 2, h = bh & 3;
  int chunk = blockIdx.x;
  int s0 = chunk * 1024;
  const float* Q  = qkv + ((size_t)b*C3 + h*CH) * HW;
  const float* Kp = qkv + ((size_t)b*C3 + CCH + h*CH) * HW;
  const float* Cn = cnf + ((size_t)b*CCH + h*CH) * HW;
  __shared__ float Qs[48][68];
  __shared__ float Ks[48][68];
  __shared__ float Cs[48][68];
  const int t = threadIdx.x;
  const int tx = t & 15, ty = t >> 4;
  float aqk[3][3] = {}, ack[3][3] = {};
  float psq[3] = {}, psk[3] = {}, psc[3] = {}, psd[3] = {};
  for (int sc = 0; sc < 1024; sc += 64) {
    #pragma unroll
    for (int i = 0; i < 3; i++) {
      int e = t + i * 256;
      int row = e >> 4;
      int col = (e & 15) * 4;
      float4 q4 = *(const float4*)&Q [(size_t)row*HW + s0 + sc + col];
      float4 c4 = *(const float4*)&Cn[(size_t)row*HW + s0 + sc + col];
      float4 k4 = *(const float4*)&Kp[(size_t)row*HW + s0 + sc + col];
      *(float4*)&Qs[row][col] = q4;
      *(float4*)&Cs[row][col] = c4;
      *(float4*)&Ks[row][col] = k4;
      psq[i] += q4.x*q4.x + q4.y*q4.y + q4.z*q4.z + q4.w*q4.w;
      psk[i] += k4.x*k4.x + k4.y*k4.y + k4.z*k4.z + k4.w*k4.w;
      psc[i] += c4.x*c4.x + c4.y*c4.y + c4.z*c4.z + c4.w*c4.w;
      psd[i] += q4.x*c4.x + q4.y*c4.y + q4.z*c4.z + q4.w*c4.w;
    }
    __syncthreads();
    #pragma unroll 4
    for (int s = 0; s < 64; s++) {
      float qv0 = Qs[ty*3+0][s], qv1 = Qs[ty*3+1][s], qv2 = Qs[ty*3+2][s];
      float cv0 = Cs[ty*3+0][s], cv1 = Cs[ty*3+1][s], cv2 = Cs[ty*3+2][s];
      float kv0 = Ks[tx*3+0][s], kv1 = Ks[tx*3+1][s], kv2 = Ks[tx*3+2][s];
      aqk[0][0]+=qv0*kv0; aqk[0][1]+=qv0*kv1; aqk[0][2]+=qv0*kv2;
      aqk[1][0]+=qv1*kv0; aqk[1][1]+=qv1*kv1; aqk[1][2]+=qv1*kv2;
      aqk[2][0]+=qv2*kv0; aqk[2][1]+=qv2*kv1; aqk[2][2]+=qv2*kv2;
      ack[0][0]+=cv0*kv0; ack[0][1]+=cv0*kv1; ack[0][2]+=cv0*kv2;
      ack[1][0]+=cv1*kv0; ack[1][1]+=cv1*kv1; ack[1][2]+=cv1*kv2;
      ack[2][0]+=cv2*kv0; ack[2][1]+=cv2*kv1; ack[2][2]+=cv2*kv2;
    }
    __syncthreads();
  }
  size_t gbase = ((size_t)chunk * 32 + bh) * CH * CH;
  #pragma unroll
  for (int i = 0; i < 3; i++)
    #pragma unroll
    for (int j = 0; j < 3; j++) {
      Gqk[gbase + (size_t)(ty*3+i)*CH + tx*3+j] = aqk[i][j];
      Gck[gbase + (size_t)(ty*3+i)*CH + tx*3+j] = ack[i][j];
    }
  #pragma unroll
  for (int i = 0; i < 3; i++) {
    int row = (t + i * 256) >> 4;
    float vq = psq[i], vk = psk[i], vc = psc[i], vd = psd[i];
    #pragma unroll
    for (int o = 8; o > 0; o >>= 1) {
      vq += __shfl_down_sync(0xffffffffu, vq, o, 16);
      vk += __shfl_down_sync(0xffffffffu, vk, o, 16);
      vc += __shfl_down_sync(0xffffffffu, vc, o, 16);
      vd += __shfl_down_sync(0xffffffffu, vd, o, 16);
    }
    if ((t & 15) == 0) {
      size_t nb = (((size_t)chunk * 32 + bh) * 4) * CH;
      Np[nb + 0*CH + row] = vq;
      Np[nb + 1*CH + row] = vk;
      Np[nb + 2*CH + row] = vc;
      Np[nb + 3*CH + row] = vd;
    }
  }
}

// ---------------- scalars: reduce norm partials -> alpha, beta, invk --------
__global__ __launch_bounds__(48) void scalars_k(
    const float* __restrict__ Np, float* __restrict__ alpha,
    float* __restrict__ beta, float* __restrict__ invk)
{
  int bh = blockIdx.x; int b = bh >> 2, h = bh & 3;
  int c = threadIdx.x;
  float Sq = 0, Sk = 0, Sc = 0, Sd = 0;
  for (int ch = 0; ch < 16; ch++) {
    size_t nb = (((size_t)ch * 32 + bh) * 4) * CH;
    Sq += Np[nb + 0*CH + c];
    Sk += Np[nb + 1*CH + c];
    Sc += Np[nb + 2*CH + c];
    Sd += Np[nb + 3*CH + c];
  }
  float a  = fmaxf(sqrtf(Sq), EPSV);
  float bb = fmaxf(sqrtf(Sc), EPSV);
  float n2 = Sq/(a*a) + 2.f*Sd/(a*bb) + Sc/(bb*bb);
  float dn = fmaxf(sqrtf(fmaxf(n2, 0.f)), EPSV);
  int bc = b*CCH + h*CH + c;
  alpha[bc] = 1.f / (a * dn);
  beta [bc] = 1.f / (bb * dn);
  invk [bc] = 1.f / fmaxf(sqrtf(Sk), EPSV);
}

// ---------------- softmax over d of t*ik_d*(al_c Gqk + be_c Gck) ------------
__global__ __launch_bounds__(32) void softmax2_k(
    const float* __restrict__ Gqk, const float* __restrict__ Gck,
    const float* __restrict__ alpha, const float* __restrict__ beta,
    const float* __restrict__ invk, const float* __restrict__ temp,
    float* __restrict__ attn)
{
  int row = blockIdx.x;            // bh*48 + c
  int bh = row / CH;
  int c  = row - bh * CH;
  int b  = bh >> 2, h = bh & 3;
  int lane = threadIdx.x;
  float tv = temp[h];
  float al = alpha[b*CCH + h*CH + c];
  float be = beta [b*CCH + h*CH + c];
  bool has1 = (lane + 32) < CH;
  float ik0 = invk[b*CCH + h*CH + lane];
  float ik1 = has1 ? invk[b*CCH + h*CH + lane + 32] : 0.f;
  float gq0 = 0, gc0 = 0, gq1 = 0, gc1 = 0;
  for (int ch = 0; ch < 16; ch++) {
    size_t base = (((size_t)ch*32 + bh)*CH + c)*CH;
    gq0 += Gqk[base + lane]; gc0 += Gck[base + lane];
    if (has1) { gq1 += Gqk[base + lane + 32]; gc1 += Gck[base + lane + 32]; }
  }
  float v0 = (al * gq0 + be * gc0) * ik0 * tv;
  float v1 = (al * gq1 + be * gc1) * ik1 * tv;
  float m = has1 ? fmaxf(v0, v1) : v0;
  #pragma unroll
  for (int o = 16; o > 0; o >>= 1) m = fmaxf(m, __shfl_xor_sync(0xffffffffu, m, o));
  float e0 = __expf(v0 - m);
  float e1 = has1 ? __expf(v1 - m) : 0.f;
  float s = e0 + e1;
  #pragma unroll
  for (int o = 16; o > 0; o >>= 1) s += __shfl_xor_sync(0xffffffffu, s, o);
  float inv = 1.f / s;
  attn[(size_t)row*CH + lane] = e0 * inv;
  if (has1) attn[(size_t)row*CH + lane + 32] = e1 * inv;
}

// ---------------- M = P @ blockdiag(attn): per-batch fused proj weights ----
__global__ __launch_bounds__(192) void pa_k(
    const float* __restrict__ P, const float* __restrict__ attn,
    float* __restrict__ M)
{
  int bh = blockIdx.x; int b = bh >> 2, h = bh & 3;
  __shared__ float As[48][49];
  const int t = threadIdx.x;
  for (int e = t; e < 48*48; e += 192)
    As[e / 48][e % 48] = attn[(size_t)bh * CH * CH + e];
  __syncthreads();
  float pr[48];
  #pragma unroll
  for (int c = 0; c < 48; c++)
    pr[c] = P[(size_t)t * CCH + h * CH + c];
  #pragma unroll 4
  for (int d = 0; d < 48; d++) {
    float s = 0.f;
    #pragma unroll
    for (int c = 0; c < 48; c++) s += pr[c] * As[c][d];
    M[((size_t)b * CCH + t) * CCH + h * CH + d] = s;
  }
}

// ---------------- launch -----------------------------------------------------
extern "C" void kernel_launch(void* const* d_in, const int* in_sizes, int n_in,
                              void* d_out, int out_size)
{
  const float* x        = (const float*)d_in[0];
  const float* cn       = (const float*)d_in[1];
  const float* cn_w1    = (const float*)d_in[2];
  const float* cn_w3    = (const float*)d_in[3];
  const float* qkv_w    = (const float*)d_in[4];
  const float* qkv_dw_w = (const float*)d_in[5];
  const float* proj_w   = (const float*)d_in[6];
  const float* temp     = (const float*)d_in[7];
  float* out = (float*)d_out;

  float *cn1, *cnf, *qkv1, *qkv, *al, *be, *ik, *Gqk, *Gck, *Np, *at, *Mw;
  cudaGetSymbolAddress((void**)&cn1,  g_cn1);
  cudaGetSymbolAddress((void**)&cnf,  g_cnf);
  cudaGetSymbolAddress((void**)&qkv1, g_qkv1);
  cudaGetSymbolAddress((void**)&qkv,  g_qkv);
  cudaGetSymbolAddress((void**)&al,   g_alpha);
  cudaGetSymbolAddress((void**)&be,   g_beta);
  cudaGetSymbolAddress((void**)&ik,   g_invk);
  cudaGetSymbolAddress((void**)&Gqk,  g_Gqk);
  cudaGetSymbolAddress((void**)&Gck,  g_Gck);
  cudaGetSymbolAddress((void**)&Np,   g_Np);
  cudaGetSymbolAddress((void**)&at,   g_attn);
  cudaGetSymbolAddress((void**)&Mw,   g_M);

  dim3 g1(HW/128, 1, NB);
  gemm1x1_fp16<<<g1, 256>>>(cn_w1, cn, cn1, CCH,
                            0, (size_t)CCH*HW, (size_t)CCH*HW);
  conv3x3_fp16<<<g1, 256>>>(cn_w3, cn1, cnf);

  dim3 g2(HW/128, 3, NB);
  gemm1x1_fp16<<<g2, 256>>>(qkv_w, x, qkv1, CCH,
                            0, (size_t)CCH*HW, (size_t)C3*HW);

  size_t ndw4 = (size_t)NB * C3 * HW / 4;
  dwconv4_k<<<(unsigned)(ndw4 / 256), 256>>>(qkv1, qkv_dw_w, qkv);

  logits2_k<<<dim3(16, NB*NHEAD), 256>>>(qkv, cnf, Gqk, Gck, Np);
  scalars_k<<<NB*NHEAD, 48>>>(Np, al, be, ik);
  softmax2_k<<<NB*NHEAD*CH, 32>>>(Gqk, Gck, al, be, ik, temp, at);
  pa_k<<<NB*NHEAD, 192>>>(proj_w, at, Mw);

  // fused (attn@v + proj): out_b = M_b @ v_b
  gemm1x1_fp16<<<g1, 256>>>(Mw, qkv + (size_t)2*CCH*HW, out, CCH,
                            (size_t)CCH*CCH, (size_t)C3*HW, (size_t)CCH*HW);
}

// round 9
// speedup vs baseline: 2.7472x; 1.0118x over previous
#include <cuda_runtime.h>
#include <cuda_fp16.h>
#include <math.h>
#include <stdint.h>

#define HW    16384
#define WID   128
#define CCH   192
#define C3    576
#define NB    8
#define NHEAD 4
#define CH    48
#define EPSV  1e-12f

// ---------------- scratch (device globals; allocation-free) ----------------
__device__ __align__(16) __half g_cn1 [(size_t)NB*CCH*HW];   // fp16 intermediate
__device__ __align__(16) float  g_cnf [(size_t)NB*CCH*HW];
__device__ __align__(16) __half g_qkv1[(size_t)NB*C3 *HW];   // fp16 intermediate
__device__ __align__(16) float  g_qkv [(size_t)NB*C3 *HW];
__device__ float g_alpha[NB*CCH];
__device__ float g_beta [NB*CCH];
__device__ float g_invk [NB*CCH];
__device__ float g_Gqk [(size_t)16*32*CH*CH];
__device__ float g_Gck [(size_t)16*32*CH*CH];
__device__ float g_Np  [(size_t)16*32*4*CH];
__device__ float g_attn[(size_t)NB*NHEAD*CH*CH];
__device__ float g_M   [(size_t)NB*CCH*CCH];

__device__ __forceinline__ uint32_t pack_h2(float lo, float hi) {
  __half2 h = __floats2half2_rn(lo, hi);
  return *(uint32_t*)&h;
}
__device__ __forceinline__ uint32_t pack_hh(__half lo, __half hi) {
  __half2 h = __halves2half2(lo, hi);
  return *(uint32_t*)&h;
}
__device__ __forceinline__ void store2(float* p, float a, float b) {
  *(float2*)p = make_float2(a, b);
}
__device__ __forceinline__ void store2(__half* p, float a, float b) {
  *(uint32_t*)p = pack_h2(a, b);
}
__device__ __forceinline__ void mma_fp16(float* c, const uint32_t* a, const uint32_t* b) {
  asm volatile(
    "mma.sync.aligned.m16n8k16.row.col.f32.f16.f16.f32 "
    "{%0,%1,%2,%3},{%4,%5,%6,%7},{%8,%9},{%0,%1,%2,%3};"
    : "+f"(c[0]), "+f"(c[1]), "+f"(c[2]), "+f"(c[3])
    : "r"(a[0]), "r"(a[1]), "r"(a[2]), "r"(a[3]), "r"(b[0]), "r"(b[1]));
}

// ================ fp16 tensor-core GEMM (1x1 conv / batched W) ==============
// Y[b, m, n] = sum_k W_b[m,k] X_b[k,n].  CTA tile 192(M) x 128(N), BK=16.
// Double-buffered smem: one sync per K-iter; STS overlaps HMMA.
#define AST 200
#define BST 136

template <typename OutT>
__global__ __launch_bounds__(256, 1) void gemm1x1_fp16(
    const float* __restrict__ Wm, const float* __restrict__ X,
    OutT* __restrict__ Y, int K,
    size_t wstride, size_t xstride, size_t ystride)
{
  const int b  = blockIdx.z;
  const int m0 = blockIdx.y * 192;
  const int n0 = blockIdx.x * 128;
  const float* Wb = Wm + (size_t)b * wstride;
  const float* Xb = X + (size_t)b * xstride;
  OutT* Yb = Y + (size_t)b * ystride;

  __shared__ uint32_t As2[2][8][AST];
  __shared__ uint32_t Bs2[2][8][BST];

  const int t    = threadIdx.x;
  const int wid  = t >> 5, lane = t & 31;
  const int wm   = wid >> 1, wn = wid & 1;
  const int grp  = lane >> 2, t4 = lane & 3;

  float acc[3][8][4] = {};

  const int bk2 = t >> 5;
  const int bng = (t & 31) * 4;

  float4 pa[3], pb0, pb1;
  // ---- preload k-tile 0 into buffer 0 ----
  #pragma unroll
  for (int i = 0; i < 3; i++) {
    int e = t + i * 256; int row = e >> 2, kf = (e & 3) * 4;
    pa[i] = *(const float4*)&Wb[(size_t)(m0 + row) * K + kf];
  }
  pb0 = *(const float4*)&Xb[(size_t)(2 * bk2    ) * HW + n0 + bng];
  pb1 = *(const float4*)&Xb[(size_t)(2 * bk2 + 1) * HW + n0 + bng];
  #pragma unroll
  for (int i = 0; i < 3; i++) {
    int e = t + i * 256; int row = e >> 2, k2 = (e & 3) * 2;
    As2[0][k2  ][row] = pack_h2(pa[i].x, pa[i].y);
    As2[0][k2+1][row] = pack_h2(pa[i].z, pa[i].w);
  }
  {
    uint4 u = make_uint4(pack_h2(pb0.x, pb1.x), pack_h2(pb0.y, pb1.y),
                         pack_h2(pb0.z, pb1.z), pack_h2(pb0.w, pb1.w));
    *(uint4*)&Bs2[0][bk2][bng] = u;
  }
  __syncthreads();

  int p = 0;
  for (int k0 = 0; k0 < K; k0 += 16) {
    bool more = (k0 + 16) < K;
    if (more) {
      #pragma unroll
      for (int i = 0; i < 3; i++) {
        int e = t + i * 256; int row = e >> 2, kf = (e & 3) * 4;
        pa[i] = *(const float4*)&Wb[(size_t)(m0 + row) * K + k0 + 16 + kf];
      }
      pb0 = *(const float4*)&Xb[(size_t)(k0 + 16 + 2 * bk2    ) * HW + n0 + bng];
      pb1 = *(const float4*)&Xb[(size_t)(k0 + 16 + 2 * bk2 + 1) * HW + n0 + bng];
    }
    {
      uint32_t af[3][4], bf[8][2];
      #pragma unroll
      for (int mt = 0; mt < 3; mt++) {
        int mb = wm * 48 + mt * 16 + grp;
        af[mt][0] = As2[p][t4    ][mb];     af[mt][1] = As2[p][t4    ][mb + 8];
        af[mt][2] = As2[p][t4 + 4][mb];     af[mt][3] = As2[p][t4 + 4][mb + 8];
      }
      #pragma unroll
      for (int nt = 0; nt < 8; nt++) {
        int nb = wn * 64 + nt * 8 + grp;
        bf[nt][0] = Bs2[p][t4][nb]; bf[nt][1] = Bs2[p][t4 + 4][nb];
      }
      #pragma unroll
      for (int mt = 0; mt < 3; mt++)
        #pragma unroll
        for (int nt = 0; nt < 8; nt++)
          mma_fp16(acc[mt][nt], af[mt], bf[nt]);
    }
    if (more) {
      #pragma unroll
      for (int i = 0; i < 3; i++) {
        int e = t + i * 256; int row = e >> 2, k2 = (e & 3) * 2;
        As2[1-p][k2  ][row] = pack_h2(pa[i].x, pa[i].y);
        As2[1-p][k2+1][row] = pack_h2(pa[i].z, pa[i].w);
      }
      uint4 u = make_uint4(pack_h2(pb0.x, pb1.x), pack_h2(pb0.y, pb1.y),
                           pack_h2(pb0.z, pb1.z), pack_h2(pb0.w, pb1.w));
      *(uint4*)&Bs2[1-p][bk2][bng] = u;
    }
    __syncthreads();
    p ^= 1;
  }

  #pragma unroll
  for (int mt = 0; mt < 3; mt++) {
    #pragma unroll
    for (int nt = 0; nt < 8; nt++) {
      int mr = m0 + wm * 48 + mt * 16 + grp;
      int nc = n0 + wn * 64 + nt * 8 + t4 * 2;
      store2(&Yb[(size_t)mr * HW + nc], acc[mt][nt][0], acc[mt][nt][1]);
      store2(&Yb[(size_t)(mr + 8) * HW + nc], acc[mt][nt][2], acc[mt][nt][3]);
    }
  }
}

// ============= fp16 implicit-GEMM 3x3 conv, fp16 activations ================
// K = 192*9 = 1728. N tile = 128 = one full image row (y = blockIdx.x).
__global__ __launch_bounds__(256, 1) void conv3x3_fp16(
    const float* __restrict__ Wm, const __half* __restrict__ X,
    float* __restrict__ Y)
{
  const int Ktot = CCH * 9;
  const int b = blockIdx.z;
  const int y = blockIdx.x;
  const __half* Xb = X + (size_t)b * CCH * HW;
  float* Yb = Y + (size_t)b * CCH * HW;

  __shared__ uint32_t As2[2][8][AST];
  __shared__ uint32_t Bs2[2][8][BST];

  const int t   = threadIdx.x;
  const int wid = t >> 5, lane = t & 31;
  const int wm  = wid >> 1, wn = wid & 1;
  const int grp = lane >> 2, t4 = lane & 3;

  float acc[3][8][4] = {};

  const int bk2 = t >> 5;
  const int bng = (t & 31) * 4;

  const __half hz = __float2half(0.f);
  auto gatherB = [&](int kglob, __half* o) {
    int ci = kglob / 9;
    int r  = kglob - ci * 9;
    int ky = r / 3;
    int kx = r - ky * 3;
    int yy = y + ky - 1;
    bool rowok = (yy >= 0) & (yy < WID);
    const __half* src = Xb + (size_t)ci * HW + yy * WID;
    #pragma unroll
    for (int j = 0; j < 4; j++) {
      int xx = bng + j + kx - 1;
      o[j] = (rowok && xx >= 0 && xx < WID) ? src[xx] : hz;
    }
  };

  float4 pa[3];
  __half pb0[4], pb1[4];
  #pragma unroll
  for (int i = 0; i < 3; i++) {
    int e = t + i * 256; int row = e >> 2, kf = (e & 3) * 4;
    pa[i] = *(const float4*)&Wm[(size_t)row * Ktot + kf];
  }
  gatherB(2 * bk2, pb0);
  gatherB(2 * bk2 + 1, pb1);
  #pragma unroll
  for (int i = 0; i < 3; i++) {
    int e = t + i * 256; int row = e >> 2, k2 = (e & 3) * 2;
    As2[0][k2  ][row] = pack_h2(pa[i].x, pa[i].y);
    As2[0][k2+1][row] = pack_h2(pa[i].z, pa[i].w);
  }
  {
    uint4 u = make_uint4(pack_hh(pb0[0], pb1[0]), pack_hh(pb0[1], pb1[1]),
                         pack_hh(pb0[2], pb1[2]), pack_hh(pb0[3], pb1[3]));
    *(uint4*)&Bs2[0][bk2][bng] = u;
  }
  __syncthreads();

  int p = 0;
  for (int k0 = 0; k0 < Ktot; k0 += 16) {
    bool more = (k0 + 16) < Ktot;
    if (more) {
      #pragma unroll
      for (int i = 0; i < 3; i++) {
        int e = t + i * 256; int row = e >> 2, kf = (e & 3) * 4;
        pa[i] = *(const float4*)&Wm[(size_t)row * Ktot + k0 + 16 + kf];
      }
      gatherB(k0 + 16 + 2 * bk2, pb0);
      gatherB(k0 + 16 + 2 * bk2 + 1, pb1);
    }
    {
      uint32_t af[3][4], bf[8][2];
      #pragma unroll
      for (int mt = 0; mt < 3; mt++) {
        int mb = wm * 48 + mt * 16 + grp;
        af[mt][0] = As2[p][t4    ][mb];     af[mt][1] = As2[p][t4    ][mb + 8];
        af[mt][2] = As2[p][t4 + 4][mb];     af[mt][3] = As2[p][t4 + 4][mb + 8];
      }
      #pragma unroll
      for (int nt = 0; nt < 8; nt++) {
        int nb = wn * 64 + nt * 8 + grp;
        bf[nt][0] = Bs2[p][t4][nb]; bf[nt][1] = Bs2[p][t4 + 4][nb];
      }
      #pragma unroll
      for (int mt = 0; mt < 3; mt++)
        #pragma unroll
        for (int nt = 0; nt < 8; nt++)
          mma_fp16(acc[mt][nt], af[mt], bf[nt]);
    }
    if (more) {
      #pragma unroll
      for (int i = 0; i < 3; i++) {
        int e = t + i * 256; int row = e >> 2, k2 = (e & 3) * 2;
        As2[1-p][k2  ][row] = pack_h2(pa[i].x, pa[i].y);
        As2[1-p][k2+1][row] = pack_h2(pa[i].z, pa[i].w);
      }
      uint4 u = make_uint4(pack_hh(pb0[0], pb1[0]), pack_hh(pb0[1], pb1[1]),
                           pack_hh(pb0[2], pb1[2]), pack_hh(pb0[3], pb1[3]));
      *(uint4*)&Bs2[1-p][bk2][bng] = u;
    }
    __syncthreads();
    p ^= 1;
  }

  const int n0 = y * 128;
  #pragma unroll
  for (int mt = 0; mt < 3; mt++) {
    #pragma unroll
    for (int nt = 0; nt < 8; nt++) {
      int mr = wm * 48 + mt * 16 + grp;
      int nc = n0 + wn * 64 + nt * 8 + t4 * 2;
      *(float2*)&Yb[(size_t)mr * HW + nc] = make_float2(acc[mt][nt][0], acc[mt][nt][1]);
      *(float2*)&Yb[(size_t)(mr + 8) * HW + nc] = make_float2(acc[mt][nt][2], acc[mt][nt][3]);
    }
  }
}

// ------- depthwise 3x3 (groups = 3C), fp16 in / fp32 out, 4 outputs/thread --
__global__ __launch_bounds__(256) void dwconv4_k(
    const __half* __restrict__ in, const float* __restrict__ w,
    float* __restrict__ out)
{
  size_t i4 = (size_t)blockIdx.x * 256 + threadIdx.x;
  size_t base = i4 * 4;
  int s  = (int)(base & (HW - 1));
  size_t bc = base >> 14;
  int c = (int)(bc % C3);
  int y = s >> 7, x0 = s & 127;
  const float* wp = w + (size_t)c * 9;
  const __half* ip = in + (base - s);
  float w0=wp[0],w1=wp[1],w2=wp[2],w3=wp[3],w4=wp[4],w5=wp[5],w6=wp[6],w7=wp[7],w8=wp[8];
  float a0=0,a1=0,a2=0,a3=0;
  #pragma unroll
  for (int dy = -1; dy <= 1; dy++) {
    int yy = y + dy;
    if (yy < 0 || yy >= WID) continue;
    const __half* row = ip + yy * WID;
    __half2 c01 = *(const __half2*)&row[x0];
    __half2 c23 = *(const __half2*)&row[x0 + 2];
    float cx = __half2float(__low2half(c01));
    float cy = __half2float(__high2half(c01));
    float cz = __half2float(__low2half(c23));
    float cw = __half2float(__high2half(c23));
    float lf = (x0 > 0)   ? __half2float(row[x0 - 1]) : 0.f;
    float rt = (x0 < 124) ? __half2float(row[x0 + 4]) : 0.f;
    float r0, r1, r2;
    if (dy < 0)      { r0 = w0; r1 = w1; r2 = w2; }
    else if (dy==0)  { r0 = w3; r1 = w4; r2 = w5; }
    else             { r0 = w6; r1 = w7; r2 = w8; }
    a0 += r0*lf + r1*cx + r2*cy;
    a1 += r0*cx + r1*cy + r2*cz;
    a2 += r0*cy + r1*cz + r2*cw;
    a3 += r0*cz + r1*cw + r2*rt;
  }
  *(float4*)&out[base] = make_float4(a0, a1, a2, a3);
}

// ---- logits: raw Grams Gqk = q k^T, Gck = cn k^T + per-channel norm partials
__global__ __launch_bounds__(256) void logits2_k(
    const float* __restrict__ qkv, const float* __restrict__ cnf,
    float* __restrict__ Gqk, float* __restrict__ Gck, float* __restrict__ Np)
{
  int bh = blockIdx.y; int b = bh >> 2, h = bh & 3;
  int chunk = blockIdx.x;
  int s0 = chunk * 1024;
  const float* Q  = qkv + ((size_t)b*C3 + h*CH) * HW;
  const float* Kp = qkv + ((size_t)b*C3 + CCH + h*CH) * HW;
  const float* Cn = cnf + ((size_t)b*CCH + h*CH) * HW;
  __shared__ float Qs[48][68];
  __shared__ float Ks[48][68];
  __shared__ float Cs[48][68];
  const int t = threadIdx.x;
  const int tx = t & 15, ty = t >> 4;
  float aqk[3][3] = {}, ack[3][3] = {};
  float psq[3] = {}, psk[3] = {}, psc[3] = {}, psd[3] = {};
  for (int sc = 0; sc < 1024; sc += 64) {
    #pragma unroll
    for (int i = 0; i < 3; i++) {
      int e = t + i * 256;
      int row = e >> 4;
      int col = (e & 15) * 4;
      float4 q4 = *(const float4*)&Q [(size_t)row*HW + s0 + sc + col];
      float4 c4 = *(const float4*)&Cn[(size_t)row*HW + s0 + sc + col];
      float4 k4 = *(const float4*)&Kp[(size_t)row*HW + s0 + sc + col];
      *(float4*)&Qs[row][col] = q4;
      *(float4*)&Cs[row][col] = c4;
      *(float4*)&Ks[row][col] = k4;
      psq[i] += q4.x*q4.x + q4.y*q4.y + q4.z*q4.z + q4.w*q4.w;
      psk[i] += k4.x*k4.x + k4.y*k4.y + k4.z*k4.z + k4.w*k4.w;
      psc[i] += c4.x*c4.x + c4.y*c4.y + c4.z*c4.z + c4.w*c4.w;
      psd[i] += q4.x*c4.x + q4.y*c4.y + q4.z*c4.z + q4.w*c4.w;
    }
    __syncthreads();
    #pragma unroll 4
    for (int s = 0; s < 64; s++) {
      float qv0 = Qs[ty*3+0][s], qv1 = Qs[ty*3+1][s], qv2 = Qs[ty*3+2][s];
      float cv0 = Cs[ty*3+0][s], cv1 = Cs[ty*3+1][s], cv2 = Cs[ty*3+2][s];
      float kv0 = Ks[tx*3+0][s], kv1 = Ks[tx*3+1][s], kv2 = Ks[tx*3+2][s];
      aqk[0][0]+=qv0*kv0; aqk[0][1]+=qv0*kv1; aqk[0][2]+=qv0*kv2;
      aqk[1][0]+=qv1*kv0; aqk[1][1]+=qv1*kv1; aqk[1][2]+=qv1*kv2;
      aqk[2][0]+=qv2*kv0; aqk[2][1]+=qv2*kv1; aqk[2][2]+=qv2*kv2;
      ack[0][0]+=cv0*kv0; ack[0][1]+=cv0*kv1; ack[0][2]+=cv0*kv2;
      ack[1][0]+=cv1*kv0; ack[1][1]+=cv1*kv1; ack[1][2]+=cv1*kv2;
      ack[2][0]+=cv2*kv0; ack[2][1]+=cv2*kv1; ack[2][2]+=cv2*kv2;
    }
    __syncthreads();
  }
  size_t gbase = ((size_t)chunk * 32 + bh) * CH * CH;
  #pragma unroll
  for (int i = 0; i < 3; i++)
    #pragma unroll
    for (int j = 0; j < 3; j++) {
      Gqk[gbase + (size_t)(ty*3+i)*CH + tx*3+j] = aqk[i][j];
      Gck[gbase + (size_t)(ty*3+i)*CH + tx*3+j] = ack[i][j];
    }
  #pragma unroll
  for (int i = 0; i < 3; i++) {
    int row = (t + i * 256) >> 4;
    float vq = psq[i], vk = psk[i], vc = psc[i], vd = psd[i];
    #pragma unroll
    for (int o = 8; o > 0; o >>= 1) {
      vq += __shfl_down_sync(0xffffffffu, vq, o, 16);
      vk += __shfl_down_sync(0xffffffffu, vk, o, 16);
      vc += __shfl_down_sync(0xffffffffu, vc, o, 16);
      vd += __shfl_down_sync(0xffffffffu, vd, o, 16);
    }
    if ((t & 15) == 0) {
      size_t nb = (((size_t)chunk * 32 + bh) * 4) * CH;
      Np[nb + 0*CH + row] = vq;
      Np[nb + 1*CH + row] = vk;
      Np[nb + 2*CH + row] = vc;
      Np[nb + 3*CH + row] = vd;
    }
  }
}

// ---------------- scalars: reduce norm partials -> alpha, beta, invk --------
__global__ __launch_bounds__(48) void scalars_k(
    const float* __restrict__ Np, float* __restrict__ alpha,
    float* __restrict__ beta, float* __restrict__ invk)
{
  int bh = blockIdx.x; int b = bh >> 2, h = bh & 3;
  int c = threadIdx.x;
  float Sq = 0, Sk = 0, Sc = 0, Sd = 0;
  for (int ch = 0; ch < 16; ch++) {
    size_t nb = (((size_t)ch * 32 + bh) * 4) * CH;
    Sq += Np[nb + 0*CH + c];
    Sk += Np[nb + 1*CH + c];
    Sc += Np[nb + 2*CH + c];
    Sd += Np[nb + 3*CH + c];
  }
  float a  = fmaxf(sqrtf(Sq), EPSV);
  float bb = fmaxf(sqrtf(Sc), EPSV);
  float n2 = Sq/(a*a) + 2.f*Sd/(a*bb) + Sc/(bb*bb);
  float dn = fmaxf(sqrtf(fmaxf(n2, 0.f)), EPSV);
  int bc = b*CCH + h*CH + c;
  alpha[bc] = 1.f / (a * dn);
  beta [bc] = 1.f / (bb * dn);
  invk [bc] = 1.f / fmaxf(sqrtf(Sk), EPSV);
}

// ---------------- softmax over d of t*ik_d*(al_c Gqk + be_c Gck) ------------
__global__ __launch_bounds__(32) void softmax2_k(
    const float* __restrict__ Gqk, const float* __restrict__ Gck,
    const float* __restrict__ alpha, const float* __restrict__ beta,
    const float* __restrict__ invk, const float* __restrict__ temp,
    float* __restrict__ attn)
{
  int row = blockIdx.x;            // bh*48 + c
  int bh = row / CH;
  int c  = row - bh * CH;
  int b  = bh >> 2, h = bh & 3;
  int lane = threadIdx.x;
  float tv = temp[h];
  float al = alpha[b*CCH + h*CH + c];
  float be = beta [b*CCH + h*CH + c];
  bool has1 = (lane + 32) < CH;
  float ik0 = invk[b*CCH + h*CH + lane];
  float ik1 = has1 ? invk[b*CCH + h*CH + lane + 32] : 0.f;
  float gq0 = 0, gc0 = 0, gq1 = 0, gc1 = 0;
  for (int ch = 0; ch < 16; ch++) {
    size_t base = (((size_t)ch*32 + bh)*CH + c)*CH;
    gq0 += Gqk[base + lane]; gc0 += Gck[base + lane];
    if (has1) { gq1 += Gqk[base + lane + 32]; gc1 += Gck[base + lane + 32]; }
  }
  float v0 = (al * gq0 + be * gc0) * ik0 * tv;
  float v1 = (al * gq1 + be * gc1) * ik1 * tv;
  float m = has1 ? fmaxf(v0, v1) : v0;
  #pragma unroll
  for (int o = 16; o > 0; o >>= 1) m = fmaxf(m, __shfl_xor_sync(0xffffffffu, m, o));
  float e0 = __expf(v0 - m);
  float e1 = has1 ? __expf(v1 - m) : 0.f;
  float s = e0 + e1;
  #pragma unroll
  for (int o = 16; o > 0; o >>= 1) s += __shfl_xor_sync(0xffffffffu, s, o);
  float inv = 1.f / s;
  attn[(size_t)row*CH + lane] = e0 * inv;
  if (has1) attn[(size_t)row*CH + lane + 32] = e1 * inv;
}

// ---------------- M = P @ blockdiag(attn): per-batch fused proj weights ----
__global__ __launch_bounds__(192) void pa_k(
    const float* __restrict__ P, const float* __restrict__ attn,
    float* __restrict__ M)
{
  int bh = blockIdx.x; int b = bh >> 2, h = bh & 3;
  __shared__ float As[48][49];
  const int t = threadIdx.x;
  for (int e = t; e < 48*48; e += 192)
    As[e / 48][e % 48] = attn[(size_t)bh * CH * CH + e];
  __syncthreads();
  float pr[48];
  #pragma unroll
  for (int c = 0; c < 48; c++)
    pr[c] = P[(size_t)t * CCH + h * CH + c];
  #pragma unroll 4
  for (int d = 0; d < 48; d++) {
    float s = 0.f;
    #pragma unroll
    for (int c = 0; c < 48; c++) s += pr[c] * As[c][d];
    M[((size_t)b * CCH + t) * CCH + h * CH + d] = s;
  }
}

// ---------------- launch -----------------------------------------------------
extern "C" void kernel_launch(void* const* d_in, const int* in_sizes, int n_in,
                              void* d_out, int out_size)
{
  const float* x        = (const float*)d_in[0];
  const float* cn       = (const float*)d_in[1];
  const float* cn_w1    = (const float*)d_in[2];
  const float* cn_w3    = (const float*)d_in[3];
  const float* qkv_w    = (const float*)d_in[4];
  const float* qkv_dw_w = (const float*)d_in[5];
  const float* proj_w   = (const float*)d_in[6];
  const float* temp     = (const float*)d_in[7];
  float* out = (float*)d_out;

  __half *cn1, *qkv1;
  float *cnf, *qkv, *al, *be, *ik, *Gqk, *Gck, *Np, *at, *Mw;
  cudaGetSymbolAddress((void**)&cn1,  g_cn1);
  cudaGetSymbolAddress((void**)&cnf,  g_cnf);
  cudaGetSymbolAddress((void**)&qkv1, g_qkv1);
  cudaGetSymbolAddress((void**)&qkv,  g_qkv);
  cudaGetSymbolAddress((void**)&al,   g_alpha);
  cudaGetSymbolAddress((void**)&be,   g_beta);
  cudaGetSymbolAddress((void**)&ik,   g_invk);
  cudaGetSymbolAddress((void**)&Gqk,  g_Gqk);
  cudaGetSymbolAddress((void**)&Gck,  g_Gck);
  cudaGetSymbolAddress((void**)&Np,   g_Np);
  cudaGetSymbolAddress((void**)&at,   g_attn);
  cudaGetSymbolAddress((void**)&Mw,   g_M);

  dim3 g1(HW/128, 1, NB);
  gemm1x1_fp16<__half><<<g1, 256>>>(cn_w1, cn, cn1, CCH,
                                    0, (size_t)CCH*HW, (size_t)CCH*HW);
  conv3x3_fp16<<<g1, 256>>>(cn_w3, cn1, cnf);

  dim3 g2(HW/128, 3, NB);
  gemm1x1_fp16<__half><<<g2, 256>>>(qkv_w, x, qkv1, CCH,
                                    0, (size_t)CCH*HW, (size_t)C3*HW);

  size_t ndw4 = (size_t)NB * C3 * HW / 4;
  dwconv4_k<<<(unsigned)(ndw4 / 256), 256>>>(qkv1, qkv_dw_w, qkv);

  logits2_k<<<dim3(16, NB*NHEAD), 256>>>(qkv, cnf, Gqk, Gck, Np);
  scalars_k<<<NB*NHEAD, 48>>>(Np, al, be, ik);
  softmax2_k<<<NB*NHEAD*CH, 32>>>(Gqk, Gck, al, be, ik, temp, at);
  pa_k<<<NB*NHEAD, 192>>>(proj_w, at, Mw);

  // fused (attn@v + proj): out_b = M_b @ v_b
  gemm1x1_fp16<float><<<g1, 256>>>(Mw, qkv + (size_t)2*CCH*HW, out, CCH,
                                   (size_t)CCH*CCH, (size_t)C3*HW, (size_t)CCH*HW);
}

// round 10
// speedup vs baseline: 3.0393x; 1.1063x over previous
#include <cuda_runtime.h>
#include <cuda_fp16.h>
#include <math.h>
#include <stdint.h>

#define HW    16384
#define WID   128
#define CCH   192
#define C3    576
#define NB    8
#define NHEAD 4
#define CH    48
#define EPSV  1e-12f

// ---------------- scratch (device globals; allocation-free) ----------------
__device__ __align__(16) __half g_cn1 [(size_t)NB*CCH*HW];   // fp16 intermediate
__device__ __align__(16) float  g_cnf [(size_t)NB*CCH*HW];
__device__ __align__(16) __half g_qkv1[(size_t)NB*C3 *HW];   // fp16 intermediate
__device__ __align__(16) float  g_qkv [(size_t)NB*C3 *HW];
__device__ __align__(16) uint32_t g_Wp3[(size_t)(CCH*9/2)*CCH];  // reordered packed conv3 weights
__device__ float g_alpha[NB*CCH];
__device__ float g_beta [NB*CCH];
__device__ float g_invk [NB*CCH];
__device__ float g_Gqk [(size_t)16*32*CH*CH];
__device__ float g_Gck [(size_t)16*32*CH*CH];
__device__ float g_Np  [(size_t)16*32*4*CH];
__device__ float g_attn[(size_t)NB*NHEAD*CH*CH];
__device__ float g_M   [(size_t)NB*CCH*CCH];

__device__ __forceinline__ uint32_t pack_h2(float lo, float hi) {
  __half2 h = __floats2half2_rn(lo, hi);
  return *(uint32_t*)&h;
}
__device__ __forceinline__ uint32_t pack_hh(__half lo, __half hi) {
  __half2 h = __halves2half2(lo, hi);
  return *(uint32_t*)&h;
}
__device__ __forceinline__ void store2(float* p, float a, float b) {
  *(float2*)p = make_float2(a, b);
}
__device__ __forceinline__ void store2(__half* p, float a, float b) {
  *(uint32_t*)p = pack_h2(a, b);
}
__device__ __forceinline__ void mma_fp16(float* c, const uint32_t* a, const uint32_t* b) {
  asm volatile(
    "mma.sync.aligned.m16n8k16.row.col.f32.f16.f16.f32 "
    "{%0,%1,%2,%3},{%4,%5,%6,%7},{%8,%9},{%0,%1,%2,%3};"
    : "+f"(c[0]), "+f"(c[1]), "+f"(c[2]), "+f"(c[3])
    : "r"(a[0]), "r"(a[1]), "r"(a[2]), "r"(a[3]), "r"(b[0]), "r"(b[1]));
}

// ================ fp16 tensor-core GEMM (1x1 conv / batched W) ==============
// Y[b, m, n] = sum_k W_b[m,k] X_b[k,n].  CTA tile 192(M) x 128(N), BK=16.
#define AST 200
#define BST 136

template <typename OutT>
__global__ __launch_bounds__(256, 1) void gemm1x1_fp16(
    const float* __restrict__ Wm, const float* __restrict__ X,
    OutT* __restrict__ Y, int K,
    size_t wstride, size_t xstride, size_t ystride)
{
  const int b  = blockIdx.z;
  const int m0 = blockIdx.y * 192;
  const int n0 = blockIdx.x * 128;
  const float* Wb = Wm + (size_t)b * wstride;
  const float* Xb = X + (size_t)b * xstride;
  OutT* Yb = Y + (size_t)b * ystride;

  __shared__ uint32_t As2[2][8][AST];
  __shared__ uint32_t Bs2[2][8][BST];

  const int t    = threadIdx.x;
  const int wid  = t >> 5, lane = t & 31;
  const int wm   = wid >> 1, wn = wid & 1;
  const int grp  = lane >> 2, t4 = lane & 3;

  float acc[3][8][4] = {};

  const int bk2 = t >> 5;
  const int bng = (t & 31) * 4;

  float4 pa[3], pb0, pb1;
  #pragma unroll
  for (int i = 0; i < 3; i++) {
    int e = t + i * 256; int row = e >> 2, kf = (e & 3) * 4;
    pa[i] = *(const float4*)&Wb[(size_t)(m0 + row) * K + kf];
  }
  pb0 = *(const float4*)&Xb[(size_t)(2 * bk2    ) * HW + n0 + bng];
  pb1 = *(const float4*)&Xb[(size_t)(2 * bk2 + 1) * HW + n0 + bng];
  #pragma unroll
  for (int i = 0; i < 3; i++) {
    int e = t + i * 256; int row = e >> 2, k2 = (e & 3) * 2;
    As2[0][k2  ][row] = pack_h2(pa[i].x, pa[i].y);
    As2[0][k2+1][row] = pack_h2(pa[i].z, pa[i].w);
  }
  {
    uint4 u = make_uint4(pack_h2(pb0.x, pb1.x), pack_h2(pb0.y, pb1.y),
                         pack_h2(pb0.z, pb1.z), pack_h2(pb0.w, pb1.w));
    *(uint4*)&Bs2[0][bk2][bng] = u;
  }
  __syncthreads();

  int p = 0;
  for (int k0 = 0; k0 < K; k0 += 16) {
    bool more = (k0 + 16) < K;
    if (more) {
      #pragma unroll
      for (int i = 0; i < 3; i++) {
        int e = t + i * 256; int row = e >> 2, kf = (e & 3) * 4;
        pa[i] = *(const float4*)&Wb[(size_t)(m0 + row) * K + k0 + 16 + kf];
      }
      pb0 = *(const float4*)&Xb[(size_t)(k0 + 16 + 2 * bk2    ) * HW + n0 + bng];
      pb1 = *(const float4*)&Xb[(size_t)(k0 + 16 + 2 * bk2 + 1) * HW + n0 + bng];
    }
    {
      uint32_t af[3][4], bf[8][2];
      #pragma unroll
      for (int mt = 0; mt < 3; mt++) {
        int mb = wm * 48 + mt * 16 + grp;
        af[mt][0] = As2[p][t4    ][mb];     af[mt][1] = As2[p][t4    ][mb + 8];
        af[mt][2] = As2[p][t4 + 4][mb];     af[mt][3] = As2[p][t4 + 4][mb + 8];
      }
      #pragma unroll
      for (int nt = 0; nt < 8; nt++) {
        int nb = wn * 64 + nt * 8 + grp;
        bf[nt][0] = Bs2[p][t4][nb]; bf[nt][1] = Bs2[p][t4 + 4][nb];
      }
      #pragma unroll
      for (int mt = 0; mt < 3; mt++)
        #pragma unroll
        for (int nt = 0; nt < 8; nt++)
          mma_fp16(acc[mt][nt], af[mt], bf[nt]);
    }
    if (more) {
      #pragma unroll
      for (int i = 0; i < 3; i++) {
        int e = t + i * 256; int row = e >> 2, k2 = (e & 3) * 2;
        As2[1-p][k2  ][row] = pack_h2(pa[i].x, pa[i].y);
        As2[1-p][k2+1][row] = pack_h2(pa[i].z, pa[i].w);
      }
      uint4 u = make_uint4(pack_h2(pb0.x, pb1.x), pack_h2(pb0.y, pb1.y),
                           pack_h2(pb0.z, pb1.z), pack_h2(pb0.w, pb1.w));
      *(uint4*)&Bs2[1-p][bk2][bng] = u;
    }
    __syncthreads();
    p ^= 1;
  }

  #pragma unroll
  for (int mt = 0; mt < 3; mt++) {
    #pragma unroll
    for (int nt = 0; nt < 8; nt++) {
      int mr = m0 + wm * 48 + mt * 16 + grp;
      int nc = n0 + wn * 64 + nt * 8 + t4 * 2;
      store2(&Yb[(size_t)mr * HW + nc], acc[mt][nt][0], acc[mt][nt][1]);
      store2(&Yb[(size_t)(mr + 8) * HW + nc], acc[mt][nt][2], acc[mt][nt][3]);
    }
  }
}

// ------- conv3 weight transform: W[m][ci*9+tap] -> packed Wp[k2][m] ---------
// New K-order: k = tap*192 + ci.  Pairs (k, k+1) = consecutive ci, same tap.
__global__ __launch_bounds__(256) void wtrans3_k(
    const float* __restrict__ W, uint32_t* __restrict__ Wp)
{
  int e = blockIdx.x * 256 + threadIdx.x;       // 864*192 = 165888
  if (e >= (CCH*9/2) * CCH) return;
  int k2 = e / CCH, m = e - k2 * CCH;
  int k  = k2 * 2;
  int tap = k / CCH;
  int ci  = k - tap * CCH;
  float a = W[(size_t)m * (CCH*9) + ci * 9 + tap];
  float b = W[(size_t)m * (CCH*9) + (ci + 1) * 9 + tap];
  Wp[(size_t)k2 * CCH + m] = pack_h2(a, b);
}

// ====== fp16 conv3x3, reordered-K implicit GEMM, prepacked weights ==========
// K = 9*192 (k = tap*192 + ci).  Per K-tile: single tap -> uniform row
// predicate, coalesced channel-row gathers, A-fill is a plain uint32 copy.
__global__ __launch_bounds__(256, 1) void conv3x3_fp16(
    const uint32_t* __restrict__ Wp, const __half* __restrict__ X,
    float* __restrict__ Y)
{
  const int Ktot = CCH * 9;
  const int b = blockIdx.z;
  const int y = blockIdx.x;
  const __half* Xb = X + (size_t)b * CCH * HW;
  float* Yb = Y + (size_t)b * CCH * HW;

  __shared__ uint32_t As2[2][8][AST];
  __shared__ uint32_t Bs2[2][8][BST];

  const int t   = threadIdx.x;
  const int wid = t >> 5, lane = t & 31;
  const int wm  = wid >> 1, wn = wid & 1;
  const int grp = lane >> 2, t4 = lane & 3;

  float acc[3][8][4] = {};

  const int bk2 = t >> 5;
  const int bng = (t & 31) * 4;

  const __half hz = __float2half(0.f);

  // gather one k-pair (2 consecutive channels, same tap) for 4 x-positions
  auto gatherB = [&](int k0, uint4* u) {
    int kk  = k0 + 2 * bk2;
    int tap = kk / CCH;
    int ci  = kk - tap * CCH;
    int dy  = tap / 3 - 1;
    int dx  = tap - (tap / 3) * 3 - 1;
    int yy  = y + dy;
    __half v0[4], v1[4];
    if (yy >= 0 && yy < WID) {
      const __half* s0 = Xb + (size_t)ci * HW + yy * WID;
      const __half* s1 = s0 + HW;
      #pragma unroll
      for (int j = 0; j < 4; j++) {
        int xx = bng + j + dx;
        bool ok = (xx >= 0) & (xx < WID);
        v0[j] = ok ? s0[xx] : hz;
        v1[j] = ok ? s1[xx] : hz;
      }
    } else {
      #pragma unroll
      for (int j = 0; j < 4; j++) { v0[j] = hz; v1[j] = hz; }
    }
    *u = make_uint4(pack_hh(v0[0], v1[0]), pack_hh(v0[1], v1[1]),
                    pack_hh(v0[2], v1[2]), pack_hh(v0[3], v1[3]));
  };

  // ---- prologue: tile 0 into buffer 0 ----
  uint32_t paw[6];
  uint4 pbu;
  #pragma unroll
  for (int i = 0; i < 6; i++) {
    int e = t + i * 256; int k2l = e / 192, m = e - k2l * 192;
    paw[i] = Wp[(size_t)k2l * CCH + m];
  }
  gatherB(0, &pbu);
  #pragma unroll
  for (int i = 0; i < 6; i++) {
    int e = t + i * 256; int k2l = e / 192, m = e - k2l * 192;
    As2[0][k2l][m] = paw[i];
  }
  *(uint4*)&Bs2[0][bk2][bng] = pbu;
  __syncthreads();

  int p = 0;
  for (int k0 = 0; k0 < Ktot; k0 += 16) {
    bool more = (k0 + 16) < Ktot;
    if (more) {
      int k2base = (k0 + 16) >> 1;
      #pragma unroll
      for (int i = 0; i < 6; i++) {
        int e = t + i * 256; int k2l = e / 192, m = e - k2l * 192;
        paw[i] = Wp[(size_t)(k2base + k2l) * CCH + m];
      }
      gatherB(k0 + 16, &pbu);
    }
    {
      uint32_t af[3][4], bf[8][2];
      #pragma unroll
      for (int mt = 0; mt < 3; mt++) {
        int mb = wm * 48 + mt * 16 + grp;
        af[mt][0] = As2[p][t4    ][mb];     af[mt][1] = As2[p][t4    ][mb + 8];
        af[mt][2] = As2[p][t4 + 4][mb];     af[mt][3] = As2[p][t4 + 4][mb + 8];
      }
      #pragma unroll
      for (int nt = 0; nt < 8; nt++) {
        int nb = wn * 64 + nt * 8 + grp;
        bf[nt][0] = Bs2[p][t4][nb]; bf[nt][1] = Bs2[p][t4 + 4][nb];
      }
      #pragma unroll
      for (int mt = 0; mt < 3; mt++)
        #pragma unroll
        for (int nt = 0; nt < 8; nt++)
          mma_fp16(acc[mt][nt], af[mt], bf[nt]);
    }
    if (more) {
      #pragma unroll
      for (int i = 0; i < 6; i++) {
        int e = t + i * 256; int k2l = e / 192, m = e - k2l * 192;
        As2[1-p][k2l][m] = paw[i];
      }
      *(uint4*)&Bs2[1-p][bk2][bng] = pbu;
    }
    __syncthreads();
    p ^= 1;
  }

  const int n0 = y * 128;
  #pragma unroll
  for (int mt = 0; mt < 3; mt++) {
    #pragma unroll
    for (int nt = 0; nt < 8; nt++) {
      int mr = wm * 48 + mt * 16 + grp;
      int nc = n0 + wn * 64 + nt * 8 + t4 * 2;
      *(float2*)&Yb[(size_t)mr * HW + nc] = make_float2(acc[mt][nt][0], acc[mt][nt][1]);
      *(float2*)&Yb[(size_t)(mr + 8) * HW + nc] = make_float2(acc[mt][nt][2], acc[mt][nt][3]);
    }
  }
}

// ------- depthwise 3x3 (groups = 3C), fp16 in / fp32 out, 8 outputs/thread --
__global__ __launch_bounds__(256) void dwconv8_k(
    const __half* __restrict__ in, const float* __restrict__ w,
    float* __restrict__ out)
{
  size_t i8 = (size_t)blockIdx.x * 256 + threadIdx.x;
  size_t base = i8 * 8;
  int s  = (int)(base & (HW - 1));
  size_t bc = base >> 14;
  int c = (int)(bc % C3);
  int y = s >> 7, x0 = s & 127;          // x0 multiple of 8
  const float* wp = w + (size_t)c * 9;
  const __half* ip = in + (base - s);
  float w0=wp[0],w1=wp[1],w2=wp[2],w3=wp[3],w4=wp[4],w5=wp[5],w6=wp[6],w7=wp[7],w8=wp[8];
  float a[8] = {};
  #pragma unroll
  for (int dy = -1; dy <= 1; dy++) {
    int yy = y + dy;
    if (yy < 0 || yy >= WID) continue;
    const __half* row = ip + yy * WID;
    uint4 u = *(const uint4*)&row[x0];
    const __half2* h2 = (const __half2*)&u;
    float c8[8];
    #pragma unroll
    for (int j = 0; j < 4; j++) {
      float2 f = __half22float2(h2[j]);
      c8[2*j] = f.x; c8[2*j+1] = f.y;
    }
    float lf = (x0 > 0)   ? __half2float(row[x0 - 1]) : 0.f;
    float rt = (x0 < 120) ? __half2float(row[x0 + 8]) : 0.f;
    float r0, r1, r2;
    if (dy < 0)      { r0 = w0; r1 = w1; r2 = w2; }
    else if (dy==0)  { r0 = w3; r1 = w4; r2 = w5; }
    else             { r0 = w6; r1 = w7; r2 = w8; }
    a[0] += r0*lf + r1*c8[0] + r2*c8[1];
    #pragma unroll
    for (int j = 1; j < 7; j++)
      a[j] += r0*c8[j-1] + r1*c8[j] + r2*c8[j+1];
    a[7] += r0*c8[6] + r1*c8[7] + r2*rt;
  }
  *(float4*)&out[base]     = make_float4(a[0], a[1], a[2], a[3]);
  *(float4*)&out[base + 4] = make_float4(a[4], a[5], a[6], a[7]);
}

// ---- logits: raw Grams Gqk = q k^T, Gck = cn k^T + per-channel norm partials
__global__ __launch_bounds__(256) void logits2_k(
    const float* __restrict__ qkv, const float* __restrict__ cnf,
    float* __restrict__ Gqk, float* __restrict__ Gck, float* __restrict__ Np)
{
  int bh = blockIdx.y; int b = bh >> 2, h = bh & 3;
  int chunk = blockIdx.x;
  int s0 = chunk * 1024;
  const float* Q  = qkv + ((size_t)b*C3 + h*CH) * HW;
  const float* Kp = qkv + ((size_t)b*C3 + CCH + h*CH) * HW;
  const float* Cn = cnf + ((size_t)b*CCH + h*CH) * HW;
  __shared__ float Qs[48][68];
  __shared__ float Ks[48][68];
  __shared__ float Cs[48][68];
  const int t = threadIdx.x;
  const int tx = t & 15, ty = t >> 4;
  float aqk[3][3] = {}, ack[3][3] = {};
  float psq[3] = {}, psk[3] = {}, psc[3] = {}, psd[3] = {};
  for (int sc = 0; sc < 1024; sc += 64) {
    #pragma unroll
    for (int i = 0; i < 3; i++) {
      int e = t + i * 256;
      int row = e >> 4;
      int col = (e & 15) * 4;
      float4 q4 = *(const float4*)&Q [(size_t)row*HW + s0 + sc + col];
      float4 c4 = *(const float4*)&Cn[(size_t)row*HW + s0 + sc + col];
      float4 k4 = *(const float4*)&Kp[(size_t)row*HW + s0 + sc + col];
      *(float4*)&Qs[row][col] = q4;
      *(float4*)&Cs[row][col] = c4;
      *(float4*)&Ks[row][col] = k4;
      psq[i] += q4.x*q4.x + q4.y*q4.y + q4.z*q4.z + q4.w*q4.w;
      psk[i] += k4.x*k4.x + k4.y*k4.y + k4.z*k4.z + k4.w*k4.w;
      psc[i] += c4.x*c4.x + c4.y*c4.y + c4.z*c4.z + c4.w*c4.w;
      psd[i] += q4.x*c4.x + q4.y*c4.y + q4.z*c4.z + q4.w*c4.w;
    }
    __syncthreads();
    #pragma unroll 4
    for (int s = 0; s < 64; s++) {
      float qv0 = Qs[ty*3+0][s], qv1 = Qs[ty*3+1][s], qv2 = Qs[ty*3+2][s];
      float cv0 = Cs[ty*3+0][s], cv1 = Cs[ty*3+1][s], cv2 = Cs[ty*3+2][s];
      float kv0 = Ks[tx*3+0][s], kv1 = Ks[tx*3+1][s], kv2 = Ks[tx*3+2][s];
      aqk[0][0]+=qv0*kv0; aqk[0][1]+=qv0*kv1; aqk[0][2]+=qv0*kv2;
      aqk[1][0]+=qv1*kv0; aqk[1][1]+=qv1*kv1; aqk[1][2]+=qv1*kv2;
      aqk[2][0]+=qv2*kv0; aqk[2][1]+=qv2*kv1; aqk[2][2]+=qv2*kv2;
      ack[0][0]+=cv0*kv0; ack[0][1]+=cv0*kv1; ack[0][2]+=cv0*kv2;
      ack[1][0]+=cv1*kv0; ack[1][1]+=cv1*kv1; ack[1][2]+=cv1*kv2;
      ack[2][0]+=cv2*kv0; ack[2][1]+=cv2*kv1; ack[2][2]+=cv2*kv2;
    }
    __syncthreads();
  }
  size_t gbase = ((size_t)chunk * 32 + bh) * CH * CH;
  #pragma unroll
  for (int i = 0; i < 3; i++)
    #pragma unroll
    for (int j = 0; j < 3; j++) {
      Gqk[gbase + (size_t)(ty*3+i)*CH + tx*3+j] = aqk[i][j];
      Gck[gbase + (size_t)(ty*3+i)*CH + tx*3+j] = ack[i][j];
    }
  #pragma unroll
  for (int i = 0; i < 3; i++) {
    int row = (t + i * 256) >> 4;
    float vq = psq[i], vk = psk[i], vc = psc[i], vd = psd[i];
    #pragma unroll
    for (int o = 8; o > 0; o >>= 1) {
      vq += __shfl_down_sync(0xffffffffu, vq, o, 16);
      vk += __shfl_down_sync(0xffffffffu, vk, o, 16);
      vc += __shfl_down_sync(0xffffffffu, vc, o, 16);
      vd += __shfl_down_sync(0xffffffffu, vd, o, 16);
    }
    if ((t & 15) == 0) {
      size_t nb = (((size_t)chunk * 32 + bh) * 4) * CH;
      Np[nb + 0*CH + row] = vq;
      Np[nb + 1*CH + row] = vk;
      Np[nb + 2*CH + row] = vc;
      Np[nb + 3*CH + row] = vd;
    }
  }
}

// ---------------- scalars: reduce norm partials -> alpha, beta, invk --------
__global__ __launch_bounds__(48) void scalars_k(
    const float* __restrict__ Np, float* __restrict__ alpha,
    float* __restrict__ beta, float* __restrict__ invk)
{
  int bh = blockIdx.x; int b = bh >> 2, h = bh & 3;
  int c = threadIdx.x;
  float Sq = 0, Sk = 0, Sc = 0, Sd = 0;
  for (int ch = 0; ch < 16; ch++) {
    size_t nb = (((size_t)ch * 32 + bh) * 4) * CH;
    Sq += Np[nb + 0*CH + c];
    Sk += Np[nb + 1*CH + c];
    Sc += Np[nb + 2*CH + c];
    Sd += Np[nb + 3*CH + c];
  }
  float a  = fmaxf(sqrtf(Sq), EPSV);
  float bb = fmaxf(sqrtf(Sc), EPSV);
  float n2 = Sq/(a*a) + 2.f*Sd/(a*bb) + Sc/(bb*bb);
  float dn = fmaxf(sqrtf(fmaxf(n2, 0.f)), EPSV);
  int bc = b*CCH + h*CH + c;
  alpha[bc] = 1.f / (a * dn);
  beta [bc] = 1.f / (bb * dn);
  invk [bc] = 1.f / fmaxf(sqrtf(Sk), EPSV);
}

// ---------------- softmax over d of t*ik_d*(al_c Gqk + be_c Gck) ------------
__global__ __launch_bounds__(32) void softmax2_k(
    const float* __restrict__ Gqk, const float* __restrict__ Gck,
    const float* __restrict__ alpha, const float* __restrict__ beta,
    const float* __restrict__ invk, const float* __restrict__ temp,
    float* __restrict__ attn)
{
  int row = blockIdx.x;            // bh*48 + c
  int bh = row / CH;
  int c  = row - bh * CH;
  int b  = bh >> 2, h = bh & 3;
  int lane = threadIdx.x;
  float tv = temp[h];
  float al = alpha[b*CCH + h*CH + c];
  float be = beta [b*CCH + h*CH + c];
  bool has1 = (lane + 32) < CH;
  float ik0 = invk[b*CCH + h*CH + lane];
  float ik1 = has1 ? invk[b*CCH + h*CH + lane + 32] : 0.f;
  float gq0 = 0, gc0 = 0, gq1 = 0, gc1 = 0;
  for (int ch = 0; ch < 16; ch++) {
    size_t base = (((size_t)ch*32 + bh)*CH + c)*CH;
    gq0 += Gqk[base + lane]; gc0 += Gck[base + lane];
    if (has1) { gq1 += Gqk[base + lane + 32]; gc1 += Gck[base + lane + 32]; }
  }
  float v0 = (al * gq0 + be * gc0) * ik0 * tv;
  float v1 = (al * gq1 + be * gc1) * ik1 * tv;
  float m = has1 ? fmaxf(v0, v1) : v0;
  #pragma unroll
  for (int o = 16; o > 0; o >>= 1) m = fmaxf(m, __shfl_xor_sync(0xffffffffu, m, o));
  float e0 = __expf(v0 - m);
  float e1 = has1 ? __expf(v1 - m) : 0.f;
  float s = e0 + e1;
  #pragma unroll
  for (int o = 16; o > 0; o >>= 1) s += __shfl_xor_sync(0xffffffffu, s, o);
  float inv = 1.f / s;
  attn[(size_t)row*CH + lane] = e0 * inv;
  if (has1) attn[(size_t)row*CH + lane + 32] = e1 * inv;
}

// ---------------- M = P @ blockdiag(attn): per-batch fused proj weights ----
__global__ __launch_bounds__(192) void pa_k(
    const float* __restrict__ P, const float* __restrict__ attn,
    float* __restrict__ M)
{
  int bh = blockIdx.x; int b = bh >> 2, h = bh & 3;
  __shared__ float As[48][49];
  const int t = threadIdx.x;
  for (int e = t; e < 48*48; e += 192)
    As[e / 48][e % 48] = attn[(size_t)bh * CH * CH + e];
  __syncthreads();
  float pr[48];
  #pragma unroll
  for (int c = 0; c < 48; c++)
    pr[c] = P[(size_t)t * CCH + h * CH + c];
  #pragma unroll 4
  for (int d = 0; d < 48; d++) {
    float s = 0.f;
    #pragma unroll
    for (int c = 0; c < 48; c++) s += pr[c] * As[c][d];
    M[((size_t)b * CCH + t) * CCH + h * CH + d] = s;
  }
}

// ---------------- launch -----------------------------------------------------
extern "C" void kernel_launch(void* const* d_in, const int* in_sizes, int n_in,
                              void* d_out, int out_size)
{
  const float* x        = (const float*)d_in[0];
  const float* cn       = (const float*)d_in[1];
  const float* cn_w1    = (const float*)d_in[2];
  const float* cn_w3    = (const float*)d_in[3];
  const float* qkv_w    = (const float*)d_in[4];
  const float* qkv_dw_w = (const float*)d_in[5];
  const float* proj_w   = (const float*)d_in[6];
  const float* temp     = (const float*)d_in[7];
  float* out = (float*)d_out;

  __half *cn1, *qkv1;
  uint32_t *Wp3;
  float *cnf, *qkv, *al, *be, *ik, *Gqk, *Gck, *Np, *at, *Mw;
  cudaGetSymbolAddress((void**)&cn1,  g_cn1);
  cudaGetSymbolAddress((void**)&cnf,  g_cnf);
  cudaGetSymbolAddress((void**)&qkv1, g_qkv1);
  cudaGetSymbolAddress((void**)&qkv,  g_qkv);
  cudaGetSymbolAddress((void**)&Wp3,  g_Wp3);
  cudaGetSymbolAddress((void**)&al,   g_alpha);
  cudaGetSymbolAddress((void**)&be,   g_beta);
  cudaGetSymbolAddress((void**)&ik,   g_invk);
  cudaGetSymbolAddress((void**)&Gqk,  g_Gqk);
  cudaGetSymbolAddress((void**)&Gck,  g_Gck);
  cudaGetSymbolAddress((void**)&Np,   g_Np);
  cudaGetSymbolAddress((void**)&at,   g_attn);
  cudaGetSymbolAddress((void**)&Mw,   g_M);

  dim3 g1(HW/128, 1, NB);
  gemm1x1_fp16<__half><<<g1, 256>>>(cn_w1, cn, cn1, CCH,
                                    0, (size_t)CCH*HW, (size_t)CCH*HW);
  wtrans3_k<<<((CCH*9/2)*CCH + 255)/256, 256>>>(cn_w3, Wp3);
  conv3x3_fp16<<<g1, 256>>>(Wp3, cn1, cnf);

  dim3 g2(HW/128, 3, NB);
  gemm1x1_fp16<__half><<<g2, 256>>>(qkv_w, x, qkv1, CCH,
                                    0, (size_t)CCH*HW, (size_t)C3*HW);

  size_t ndw8 = (size_t)NB * C3 * HW / 8;
  dwconv8_k<<<(unsigned)(ndw8 / 256), 256>>>(qkv1, qkv_dw_w, qkv);

  logits2_k<<<dim3(16, NB*NHEAD), 256>>>(qkv, cnf, Gqk, Gck, Np);
  scalars_k<<<NB*NHEAD, 48>>>(Np, al, be, ik);
  softmax2_k<<<NB*NHEAD*CH, 32>>>(Gqk, Gck, al, be, ik, temp, at);
  pa_k<<<NB*NHEAD, 192>>>(proj_w, at, Mw);

  // fused (attn@v + proj): out_b = M_b @ v_b
  gemm1x1_fp16<float><<<g1, 256>>>(Mw, qkv + (size_t)2*CCH*HW, out, CCH,
                                   (size_t)CCH*CCH, (size_t)C3*HW, (size_t)CCH*HW);
}